// round 1
// baseline (speedup 1.0000x reference)
#include <cuda_runtime.h>

// Problem constants
#define CB 2
#define CL 2048
#define CD 1024
#define CH 16
#define CDK 64

constexpr int  BHn        = CB * CH;                       // 32
constexpr long PROJ_ELEMS = (long)CB * CL * CD;            // 4,194,304
constexpr long S_ELEMS    = (long)BHn * CL * CL;           // 134,217,728

// Scratch (static device globals -- no runtime allocation)
__device__ float g_Q[PROJ_ELEMS];
__device__ float g_K[PROJ_ELEMS];
__device__ float g_V[PROJ_ELEMS];
__device__ float g_S[S_ELEMS];

// ---------------------------------------------------------------------------
// Generic batched tiled GEMM, "NT" layout: C[m,n] = sum_k A[m,k] * B[n,k]
// Both A and B are k-contiguous with row strides lda/ldb.
// Per-z base offsets decompose as (z>>4)*sXo + (z&15)*sXi  (z = b*16 + h).
// Tiles: BM=BN=64, BK=16, 256 threads, 4x4 register tile per thread.
// ---------------------------------------------------------------------------
__global__ __launch_bounds__(256) void gemm_nt_kernel(
    const float* __restrict__ A, const float* __restrict__ B, float* __restrict__ C,
    int K, int lda, int ldb, int ldc,
    long sAo, long sAi, long sBo, long sBi, long sCo, long sCi)
{
    __shared__ float As[16][68];
    __shared__ float Bs[16][68];

    const int z = blockIdx.z;
    const float* Ab = A + (long)(z >> 4) * sAo + (long)(z & 15) * sAi
                        + (long)blockIdx.y * 64 * lda;
    const float* Bb = B + (long)(z >> 4) * sBo + (long)(z & 15) * sBi
                        + (long)blockIdx.x * 64 * ldb;
    float* Cb = C + (long)(z >> 4) * sCo + (long)(z & 15) * sCi
                  + (long)blockIdx.y * 64 * ldc + (long)blockIdx.x * 64;

    const int tid = threadIdx.x;
    const int tx = tid & 15, ty = tid >> 4;
    const int lr = tid >> 2;            // 0..63 : tile row to load
    const int lk = (tid & 3) << 2;      // 0,4,8,12 : k offset to load

    float acc[4][4] = {};

    for (int k0 = 0; k0 < K; k0 += 16) {
        float4 av = *(const float4*)(Ab + (long)lr * lda + k0 + lk);
        float4 bv = *(const float4*)(Bb + (long)lr * ldb + k0 + lk);
        As[lk + 0][lr] = av.x; As[lk + 1][lr] = av.y;
        As[lk + 2][lr] = av.z; As[lk + 3][lr] = av.w;
        Bs[lk + 0][lr] = bv.x; Bs[lk + 1][lr] = bv.y;
        Bs[lk + 2][lr] = bv.z; Bs[lk + 3][lr] = bv.w;
        __syncthreads();
        #pragma unroll
        for (int kk = 0; kk < 16; kk++) {
            float a[4], b[4];
            *(float4*)a = *(const float4*)&As[kk][ty * 4];
            *(float4*)b = *(const float4*)&Bs[kk][tx * 4];
            #pragma unroll
            for (int i = 0; i < 4; i++)
                #pragma unroll
                for (int j = 0; j < 4; j++)
                    acc[i][j] += a[i] * b[j];
        }
        __syncthreads();
    }

    #pragma unroll
    for (int i = 0; i < 4; i++)
        *(float4*)&Cb[(long)(ty * 4 + i) * ldc + tx * 4] = *(float4*)acc[i];
}

// ---------------------------------------------------------------------------
// Generic batched tiled GEMM, "NN" layout: C[m,n] = sum_k A[m,k] * B[k,n]
// A k-contiguous (lda), B n-contiguous (row stride ldb).
// ---------------------------------------------------------------------------
__global__ __launch_bounds__(256) void gemm_nn_kernel(
    const float* __restrict__ A, const float* __restrict__ B, float* __restrict__ C,
    int K, int lda, int ldb, int ldc,
    long sAo, long sAi, long sBo, long sBi, long sCo, long sCi)
{
    __shared__ float As[16][68];
    __shared__ float Bs[16][68];

    const int z = blockIdx.z;
    const float* Ab = A + (long)(z >> 4) * sAo + (long)(z & 15) * sAi
                        + (long)blockIdx.y * 64 * lda;
    const float* Bb = B + (long)(z >> 4) * sBo + (long)(z & 15) * sBi
                        + (long)blockIdx.x * 64;
    float* Cb = C + (long)(z >> 4) * sCo + (long)(z & 15) * sCi
                  + (long)blockIdx.y * 64 * ldc + (long)blockIdx.x * 64;

    const int tid = threadIdx.x;
    const int tx = tid & 15, ty = tid >> 4;
    const int lr = tid >> 2;            // A tile row
    const int lk = (tid & 3) << 2;      // A tile k offset
    const int bkr = tid >> 4;           // B tile k row (0..15)
    const int bnc = (tid & 15) << 2;    // B tile n col (0..60)

    float acc[4][4] = {};

    for (int k0 = 0; k0 < K; k0 += 16) {
        float4 av = *(const float4*)(Ab + (long)lr * lda + k0 + lk);
        As[lk + 0][lr] = av.x; As[lk + 1][lr] = av.y;
        As[lk + 2][lr] = av.z; As[lk + 3][lr] = av.w;
        float4 bv = *(const float4*)(Bb + (long)(k0 + bkr) * ldb + bnc);
        *(float4*)&Bs[bkr][bnc] = bv;
        __syncthreads();
        #pragma unroll
        for (int kk = 0; kk < 16; kk++) {
            float a[4], b[4];
            *(float4*)a = *(const float4*)&As[kk][ty * 4];
            *(float4*)b = *(const float4*)&Bs[kk][tx * 4];
            #pragma unroll
            for (int i = 0; i < 4; i++)
                #pragma unroll
                for (int j = 0; j < 4; j++)
                    acc[i][j] += a[i] * b[j];
        }
        __syncthreads();
    }

    #pragma unroll
    for (int i = 0; i < 4; i++)
        *(float4*)&Cb[(long)(ty * 4 + i) * ldc + tx * 4] = *(float4*)acc[i];
}

// ---------------------------------------------------------------------------
// L2 normalize each contiguous 64-float segment (one warp per segment).
// scale = coef / max(||x||, 1e-12)
// ---------------------------------------------------------------------------
__global__ __launch_bounds__(256) void l2norm_kernel(float* __restrict__ X, float coef)
{
    const int seg  = blockIdx.x * 8 + (threadIdx.x >> 5);
    const int lane = threadIdx.x & 31;
    float2* p = (float2*)(X + (long)seg * 64) + lane;
    float2 u = *p;
    float ss = u.x * u.x + u.y * u.y;
    #pragma unroll
    for (int o = 16; o; o >>= 1) ss += __shfl_xor_sync(0xffffffffu, ss, o);
    const float s = coef / fmaxf(sqrtf(ss), 1e-12f);
    u.x *= s; u.y *= s;
    *p = u;
}

// ---------------------------------------------------------------------------
// In-place row softmax: one block per row of 2048 floats.
// ---------------------------------------------------------------------------
__global__ __launch_bounds__(256) void softmax_kernel(float* __restrict__ S)
{
    float* row = S + (long)blockIdx.x * CL;
    const int t = threadIdx.x;

    float v[8];
    float m = -1e30f;
    #pragma unroll
    for (int i = 0; i < 8; i++) {
        v[i] = row[t + 256 * i];
        m = fmaxf(m, v[i]);
    }

    __shared__ float redm[8];
    __shared__ float reds[8];
    #pragma unroll
    for (int o = 16; o; o >>= 1) m = fmaxf(m, __shfl_xor_sync(0xffffffffu, m, o));
    if ((t & 31) == 0) redm[t >> 5] = m;
    __syncthreads();
    m = redm[0];
    #pragma unroll
    for (int i = 1; i < 8; i++) m = fmaxf(m, redm[i]);

    float s = 0.f;
    #pragma unroll
    for (int i = 0; i < 8; i++) {
        v[i] = __expf(v[i] - m);
        s += v[i];
    }
    #pragma unroll
    for (int o = 16; o; o >>= 1) s += __shfl_xor_sync(0xffffffffu, s, o);
    if ((t & 31) == 0) reds[t >> 5] = s;
    __syncthreads();
    s = reds[0];
    #pragma unroll
    for (int i = 1; i < 8; i++) s += reds[i];

    const float inv = 1.0f / s;
    #pragma unroll
    for (int i = 0; i < 8; i++) row[t + 256 * i] = v[i] * inv;
}

// ---------------------------------------------------------------------------
// attn_avg[b,q,k] = (1/H) * sum_h P[b,h,q,k]
// ---------------------------------------------------------------------------
__global__ __launch_bounds__(256) void head_avg_kernel(const float* __restrict__ P,
                                                       float* __restrict__ avg)
{
    const long idx = (long)blockIdx.x * 256 + threadIdx.x;  // over B*L*L
    const long b  = idx / ((long)CL * CL);
    const long qk = idx - b * (long)CL * CL;
    const float* base = P + b * (long)CH * CL * CL + qk;
    float s = 0.f;
    #pragma unroll
    for (int h = 0; h < CH; h++) s += base[(long)h * CL * CL];
    avg[idx] = s * (1.0f / CH);
}

// ---------------------------------------------------------------------------
extern "C" void kernel_launch(void* const* d_in, const int* in_sizes, int n_in,
                              void* d_out, int out_size)
{
    const float* q  = (const float*)d_in[0];
    const float* k  = (const float*)d_in[1];
    const float* v  = (const float*)d_in[2];
    const float* wq = (const float*)d_in[3];
    const float* wk = (const float*)d_in[4];
    const float* wv = (const float*)d_in[5];

    float* out = (float*)d_out;                           // [B,H,L,64]
    float* avg = out + (long)CB * CH * CL * CDK;          // [B,L,L]

    float *Qp, *Kp, *Vp, *Sp;
    cudaGetSymbolAddress((void**)&Qp, g_Q);
    cudaGetSymbolAddress((void**)&Kp, g_K);
    cudaGetSymbolAddress((void**)&Vp, g_V);
    cudaGetSymbolAddress((void**)&Sp, g_S);

    // 1) Projections: [4096,1024] x [1024,1024]^T -> [B,L,H*64] layout
    dim3 pg(CD / 64, (CB * CL) / 64, 1);
    gemm_nt_kernel<<<pg, 256>>>(q, wq, Qp, CD, CD, CD, CD, 0, 0, 0, 0, 0, 0);
    gemm_nt_kernel<<<pg, 256>>>(k, wk, Kp, CD, CD, CD, CD, 0, 0, 0, 0, 0, 0);
    gemm_nt_kernel<<<pg, 256>>>(v, wv, Vp, CD, CD, CD, CD, 0, 0, 0, 0, 0, 0);

    // 2) L2 normalize per-head vectors; fold 1/sqrt(d_k)=0.125 into Q
    l2norm_kernel<<<(CB * CL * CH) / 8, 256>>>(Qp, 0.125f);
    l2norm_kernel<<<(CB * CL * CH) / 8, 256>>>(Kp, 1.0f);

    // 3) Scores: per (b,h): S[q,k] = Qn[q,:] . Kn[k,:]   (K=64)
    dim3 sg(CL / 64, CL / 64, BHn);
    gemm_nt_kernel<<<sg, 256>>>(Qp, Kp, Sp, CDK, CD, CD, CL,
                                (long)CL * CD, 64,
                                (long)CL * CD, 64,
                                16L * CL * CL, (long)CL * CL);

    // 4) Row softmax in place (S -> P)
    softmax_kernel<<<BHn * CL, 256>>>(Sp);

    // 5) out = P @ V  (per (b,h): [2048,2048] x [2048,64])
    dim3 og(1, CL / 64, BHn);
    gemm_nn_kernel<<<og, 256>>>(Sp, Vp, out, CL, CL, CD, CDK,
                                16L * CL * CL, (long)CL * CL,
                                (long)CL * CD, 64,
                                16L * CL * CDK, (long)CL * CDK);

    // 6) attn_avg = mean over heads of P
    head_avg_kernel<<<((long)CB * CL * CL) / 256, 256>>>(Sp, avg);
}

// round 3
// speedup vs baseline: 1.8468x; 1.8468x over previous
#include <cuda_runtime.h>
#include <stdint.h>

// Problem constants
#define CB 2
#define CL 2048
#define CD 1024
#define CH 16
#define CDK 64

constexpr int  BHn        = CB * CH;               // 32
constexpr long PROJ_ELEMS = (long)CB * CL * CD;    // 4,194,304
constexpr long S_ELEMS    = (long)BHn * CL * CL;   // 134,217,728

// Scratch (static device globals -- no runtime allocation)
__device__ float g_Q[PROJ_ELEMS];
__device__ float g_K[PROJ_ELEMS];
__device__ float g_V[PROJ_ELEMS];
__device__ float g_S[S_ELEMS];

// ---------------------------------------------------------------------------
// tf32 helpers
// ---------------------------------------------------------------------------
__device__ __forceinline__ float f2tf(float x) {
    uint32_t r;
    asm("cvt.rna.tf32.f32 %0, %1;" : "=r"(r) : "f"(x));
    return __uint_as_float(r);
}

__device__ __forceinline__ void mma8(float* d, const uint32_t* a, const uint32_t* b) {
    asm volatile(
        "mma.sync.aligned.m16n8k8.row.col.f32.tf32.tf32.f32 "
        "{%0,%1,%2,%3}, {%4,%5,%6,%7}, {%8,%9}, {%0,%1,%2,%3};"
        : "+f"(d[0]), "+f"(d[1]), "+f"(d[2]), "+f"(d[3])
        : "r"(a[0]), "r"(a[1]), "r"(a[2]), "r"(a[3]), "r"(b[0]), "r"(b[1]));
}

// ---------------------------------------------------------------------------
// Batched tf32 tensor-core GEMM, NT layout: C[m,n] = sum_k A[m,k] * B[n,k]
// Both operands k-contiguous. BM=64, BN=128, BK=16, 256 threads (2x4 warps).
// Per-z batch offsets decompose as (z>>4)*sXo + (z&15)*sXi.
// ---------------------------------------------------------------------------
__global__ __launch_bounds__(256) void mma_gemm_nt(
    const float* __restrict__ A, const float* __restrict__ B, float* __restrict__ C,
    int K, int lda, int ldb, int ldc,
    long sAo, long sAi, long sBo, long sBi, long sCo, long sCi)
{
    constexpr int BM = 64, BN = 128;
    constexpr int AF4 = 1, BF4 = 2;

    __shared__ float As[BM][20];
    __shared__ float Bs[BN][20];

    const int z = blockIdx.z;
    const float* Ab = A + (long)(z >> 4) * sAo + (long)(z & 15) * sAi
                        + (long)blockIdx.y * BM * lda;
    const float* Bb = B + (long)(z >> 4) * sBo + (long)(z & 15) * sBi
                        + (long)blockIdx.x * BN * ldb;
    float* Cb = C + (long)(z >> 4) * sCo + (long)(z & 15) * sCi
                  + (long)blockIdx.y * BM * ldc + (long)blockIdx.x * BN;

    const int tid  = threadIdx.x;
    const int w    = tid >> 5;
    const int lane = tid & 31;
    const int wm   = w >> 2;       // 0..1
    const int wn   = w & 3;        // 0..3
    const int g    = lane >> 2;    // 0..7
    const int tig  = lane & 3;     // 0..3

    float acc[2][4][4];
    #pragma unroll
    for (int i = 0; i < 2; i++)
        #pragma unroll
        for (int j = 0; j < 4; j++)
            #pragma unroll
            for (int r = 0; r < 4; r++) acc[i][j][r] = 0.f;

    float4 pa[AF4], pb[BF4];

    #pragma unroll
    for (int j = 0; j < AF4; j++) {
        int f = tid + 256 * j;
        pa[j] = *(const float4*)(Ab + (long)(f >> 2) * lda + ((f & 3) << 2));
    }
    #pragma unroll
    for (int j = 0; j < BF4; j++) {
        int f = tid + 256 * j;
        pb[j] = *(const float4*)(Bb + (long)(f >> 2) * ldb + ((f & 3) << 2));
    }

    for (int k0 = 0; k0 < K; k0 += 16) {
        #pragma unroll
        for (int j = 0; j < AF4; j++) {
            int f = tid + 256 * j;
            int r = f >> 2, kq = (f & 3) << 2;
            As[r][kq + 0] = f2tf(pa[j].x); As[r][kq + 1] = f2tf(pa[j].y);
            As[r][kq + 2] = f2tf(pa[j].z); As[r][kq + 3] = f2tf(pa[j].w);
        }
        #pragma unroll
        for (int j = 0; j < BF4; j++) {
            int f = tid + 256 * j;
            int r = f >> 2, kq = (f & 3) << 2;
            Bs[r][kq + 0] = f2tf(pb[j].x); Bs[r][kq + 1] = f2tf(pb[j].y);
            Bs[r][kq + 2] = f2tf(pb[j].z); Bs[r][kq + 3] = f2tf(pb[j].w);
        }
        __syncthreads();

        if (k0 + 16 < K) {
            #pragma unroll
            for (int j = 0; j < AF4; j++) {
                int f = tid + 256 * j;
                pa[j] = *(const float4*)(Ab + (long)(f >> 2) * lda + k0 + 16 + ((f & 3) << 2));
            }
            #pragma unroll
            for (int j = 0; j < BF4; j++) {
                int f = tid + 256 * j;
                pb[j] = *(const float4*)(Bb + (long)(f >> 2) * ldb + k0 + 16 + ((f & 3) << 2));
            }
        }

        #pragma unroll
        for (int ks = 0; ks < 2; ks++) {
            const int c0 = ks * 8;
            uint32_t af[2][4], bf[4][2];
            #pragma unroll
            for (int mt = 0; mt < 2; mt++) {
                int r0 = wm * 32 + mt * 16 + g;
                af[mt][0] = __float_as_uint(As[r0][c0 + tig]);
                af[mt][1] = __float_as_uint(As[r0 + 8][c0 + tig]);
                af[mt][2] = __float_as_uint(As[r0][c0 + tig + 4]);
                af[mt][3] = __float_as_uint(As[r0 + 8][c0 + tig + 4]);
            }
            #pragma unroll
            for (int nt = 0; nt < 4; nt++) {
                int n = wn * 32 + nt * 8 + g;
                bf[nt][0] = __float_as_uint(Bs[n][c0 + tig]);
                bf[nt][1] = __float_as_uint(Bs[n][c0 + tig + 4]);
            }
            #pragma unroll
            for (int mt = 0; mt < 2; mt++)
                #pragma unroll
                for (int nt = 0; nt < 4; nt++)
                    mma8(acc[mt][nt], af[mt], bf[nt]);
        }
        __syncthreads();
    }

    #pragma unroll
    for (int mt = 0; mt < 2; mt++) {
        #pragma unroll
        for (int nt = 0; nt < 4; nt++) {
            long r0  = wm * 32 + mt * 16 + g;
            int  col = wn * 32 + nt * 8 + 2 * tig;
            *(float2*)&Cb[r0 * ldc + col]       = make_float2(acc[mt][nt][0], acc[mt][nt][1]);
            *(float2*)&Cb[(r0 + 8) * ldc + col] = make_float2(acc[mt][nt][2], acc[mt][nt][3]);
        }
    }
}

// ---------------------------------------------------------------------------
// Batched tf32 tensor-core GEMM, NN layout: C[m,n] = sum_k A[m,k] * B[k,n]
// A k-contiguous (lda), B n-contiguous (row stride ldb). BM=64, BN=64, BK=16.
// ---------------------------------------------------------------------------
__global__ __launch_bounds__(256) void mma_gemm_nn(
    const float* __restrict__ A, const float* __restrict__ B, float* __restrict__ C,
    int K, int lda, int ldb, int ldc,
    long sAo, long sAi, long sBo, long sBi, long sCo, long sCi)
{
    constexpr int BM = 64, BN = 64;

    __shared__ float As[BM][20];
    __shared__ float Bs[16][BN + 4];

    const int z = blockIdx.z;
    const float* Ab = A + (long)(z >> 4) * sAo + (long)(z & 15) * sAi
                        + (long)blockIdx.y * BM * lda;
    const float* Bb = B + (long)(z >> 4) * sBo + (long)(z & 15) * sBi
                        + (long)blockIdx.x * BN;
    float* Cb = C + (long)(z >> 4) * sCo + (long)(z & 15) * sCi
                  + (long)blockIdx.y * BM * ldc + (long)blockIdx.x * BN;

    const int tid  = threadIdx.x;
    const int w    = tid >> 5;
    const int lane = tid & 31;
    const int wm   = w >> 2;       // 0..1
    const int wn   = w & 3;        // 0..3
    const int g    = lane >> 2;    // 0..7
    const int tig  = lane & 3;     // 0..3

    const int lr  = tid >> 2;          // A row to load
    const int lk  = (tid & 3) << 2;    // A k offset
    const int bkr = tid >> 4;          // B k row (0..15)
    const int bnc = (tid & 15) << 2;   // B n col

    float acc[2][2][4];
    #pragma unroll
    for (int i = 0; i < 2; i++)
        #pragma unroll
        for (int j = 0; j < 2; j++)
            #pragma unroll
            for (int r = 0; r < 4; r++) acc[i][j][r] = 0.f;

    float4 pa = *(const float4*)(Ab + (long)lr * lda + lk);
    float4 pb = *(const float4*)(Bb + (long)bkr * ldb + bnc);

    for (int k0 = 0; k0 < K; k0 += 16) {
        As[lr][lk + 0] = f2tf(pa.x); As[lr][lk + 1] = f2tf(pa.y);
        As[lr][lk + 2] = f2tf(pa.z); As[lr][lk + 3] = f2tf(pa.w);
        Bs[bkr][bnc + 0] = f2tf(pb.x); Bs[bkr][bnc + 1] = f2tf(pb.y);
        Bs[bkr][bnc + 2] = f2tf(pb.z); Bs[bkr][bnc + 3] = f2tf(pb.w);
        __syncthreads();

        if (k0 + 16 < K) {
            pa = *(const float4*)(Ab + (long)lr * lda + k0 + 16 + lk);
            pb = *(const float4*)(Bb + (long)(k0 + 16 + bkr) * ldb + bnc);
        }

        #pragma unroll
        for (int ks = 0; ks < 2; ks++) {
            const int c0 = ks * 8;
            uint32_t af[2][4], bf[2][2];
            #pragma unroll
            for (int mt = 0; mt < 2; mt++) {
                int r0 = wm * 32 + mt * 16 + g;
                af[mt][0] = __float_as_uint(As[r0][c0 + tig]);
                af[mt][1] = __float_as_uint(As[r0 + 8][c0 + tig]);
                af[mt][2] = __float_as_uint(As[r0][c0 + tig + 4]);
                af[mt][3] = __float_as_uint(As[r0 + 8][c0 + tig + 4]);
            }
            #pragma unroll
            for (int nt = 0; nt < 2; nt++) {
                int n = wn * 16 + nt * 8 + g;
                bf[nt][0] = __float_as_uint(Bs[c0 + tig][n]);
                bf[nt][1] = __float_as_uint(Bs[c0 + tig + 4][n]);
            }
            #pragma unroll
            for (int mt = 0; mt < 2; mt++)
                #pragma unroll
                for (int nt = 0; nt < 2; nt++)
                    mma8(acc[mt][nt], af[mt], bf[nt]);
        }
        __syncthreads();
    }

    #pragma unroll
    for (int mt = 0; mt < 2; mt++) {
        #pragma unroll
        for (int nt = 0; nt < 2; nt++) {
            long r0  = wm * 32 + mt * 16 + g;
            int  col = wn * 16 + nt * 8 + 2 * tig;
            *(float2*)&Cb[r0 * ldc + col]       = make_float2(acc[mt][nt][0], acc[mt][nt][1]);
            *(float2*)&Cb[(r0 + 8) * ldc + col] = make_float2(acc[mt][nt][2], acc[mt][nt][3]);
        }
    }
}

// ---------------------------------------------------------------------------
// L2 normalize each contiguous 64-float segment (one warp per segment).
// ---------------------------------------------------------------------------
__global__ __launch_bounds__(256) void l2norm_kernel(float* __restrict__ X, float coef)
{
    const int seg  = blockIdx.x * 8 + (threadIdx.x >> 5);
    const int lane = threadIdx.x & 31;
    float2* p = (float2*)(X + (long)seg * 64) + lane;
    float2 u = *p;
    float ss = u.x * u.x + u.y * u.y;
    #pragma unroll
    for (int o = 16; o; o >>= 1) ss += __shfl_xor_sync(0xffffffffu, ss, o);
    const float s = coef / fmaxf(sqrtf(ss), 1e-12f);
    u.x *= s; u.y *= s;
    *p = u;
}

// ---------------------------------------------------------------------------
// Fused: in-place softmax for all 16 heads of one (b,q) + head average.
// ---------------------------------------------------------------------------
__global__ __launch_bounds__(256) void softmax_avg_kernel(float* __restrict__ S,
                                                          float* __restrict__ avg)
{
    const int b = blockIdx.x >> 11;
    const int q = blockIdx.x & 2047;
    const int t = threadIdx.x;
    const int w = t >> 5, lane = t & 31;

    __shared__ float red[8];
    float acc[8];
    #pragma unroll
    for (int i = 0; i < 8; i++) acc[i] = 0.f;

    for (int h = 0; h < CH; h++) {
        float* row = S + ((long)(b * CH + h) * CL + q) * CL;
        float v[8];
        float m = -1e30f;
        #pragma unroll
        for (int i = 0; i < 8; i++) {
            v[i] = row[t + 256 * i];
            m = fmaxf(m, v[i]);
        }
        #pragma unroll
        for (int o = 16; o; o >>= 1) m = fmaxf(m, __shfl_xor_sync(0xffffffffu, m, o));
        if (lane == 0) red[w] = m;
        __syncthreads();
        m = red[0];
        #pragma unroll
        for (int i = 1; i < 8; i++) m = fmaxf(m, red[i]);
        __syncthreads();

        float s = 0.f;
        #pragma unroll
        for (int i = 0; i < 8; i++) {
            v[i] = __expf(v[i] - m);
            s += v[i];
        }
        #pragma unroll
        for (int o = 16; o; o >>= 1) s += __shfl_xor_sync(0xffffffffu, s, o);
        if (lane == 0) red[w] = s;
        __syncthreads();
        s = red[0];
        #pragma unroll
        for (int i = 1; i < 8; i++) s += red[i];

        const float inv = 1.0f / s;
        #pragma unroll
        for (int i = 0; i < 8; i++) {
            float p = v[i] * inv;
            row[t + 256 * i] = p;
            acc[i] += p;
        }
        __syncthreads();
    }

    float* arow = avg + ((long)b * CL + q) * CL;
    #pragma unroll
    for (int i = 0; i < 8; i++) arow[t + 256 * i] = acc[i] * (1.0f / CH);
}

// ---------------------------------------------------------------------------
extern "C" void kernel_launch(void* const* d_in, const int* in_sizes, int n_in,
                              void* d_out, int out_size)
{
    const float* q  = (const float*)d_in[0];
    const float* k  = (const float*)d_in[1];
    const float* v  = (const float*)d_in[2];
    const float* wq = (const float*)d_in[3];
    const float* wk = (const float*)d_in[4];
    const float* wv = (const float*)d_in[5];

    float* out = (float*)d_out;                        // [B,H,L,64]
    float* avg = out + (long)CB * CH * CL * CDK;       // [B,L,L]

    float *Qp, *Kp, *Vp, *Sp;
    cudaGetSymbolAddress((void**)&Qp, g_Q);
    cudaGetSymbolAddress((void**)&Kp, g_K);
    cudaGetSymbolAddress((void**)&Vp, g_V);
    cudaGetSymbolAddress((void**)&Sp, g_S);

    // 1) Projections: [4096,1024] x [1024,1024]^T (tf32 MMA)
    dim3 pg(CD / 128, (CB * CL) / 64, 1);
    mma_gemm_nt<<<pg, 256>>>(q, wq, Qp, CD, CD, CD, CD, 0, 0, 0, 0, 0, 0);
    mma_gemm_nt<<<pg, 256>>>(k, wk, Kp, CD, CD, CD, CD, 0, 0, 0, 0, 0, 0);
    mma_gemm_nt<<<pg, 256>>>(v, wv, Vp, CD, CD, CD, CD, 0, 0, 0, 0, 0, 0);

    // 2) L2 normalize per-head vectors; fold 1/sqrt(d_k)=0.125 into Q
    l2norm_kernel<<<(CB * CL * CH) / 8, 256>>>(Qp, 0.125f);
    l2norm_kernel<<<(CB * CL * CH) / 8, 256>>>(Kp, 1.0f);

    // 3) Scores: per (b,h): S[q,k] = Qn[q,:] . Kn[k,:]   (K=64, tf32 MMA)
    dim3 sg(CL / 128, CL / 64, BHn);
    mma_gemm_nt<<<sg, 256>>>(Qp, Kp, Sp, CDK, CD, CD, CL,
                             (long)CL * CD, 64,
                             (long)CL * CD, 64,
                             16L * CL * CL, (long)CL * CL);

    // 4) Fused row softmax (in place) + head average
    softmax_avg_kernel<<<CB * CL, 256>>>(Sp, avg);

    // 5) out = P @ V  (per (b,h): [2048,2048] x [2048,64], tf32 MMA, NN)
    dim3 og(1, CL / 64, BHn);
    mma_gemm_nn<<<og, 256>>>(Sp, Vp, out, CL, CL, CD, CDK,
                             16L * CL * CL, (long)CL * CL,
                             (long)CL * CD, 64,
                             16L * CL * CDK, (long)CL * CDK);
}

// round 4
// speedup vs baseline: 2.2976x; 1.2441x over previous
#include <cuda_runtime.h>
#include <cuda_fp16.h>
#include <stdint.h>

// Problem constants
#define CB 2
#define CL 2048
#define CD 1024
#define CH 16
#define CDK 64

constexpr int  BHn        = CB * CH;               // 32
constexpr long PROJ_ELEMS = (long)CB * CL * CD;    // 4,194,304
constexpr long S_ELEMS    = (long)BHn * CL * CL;   // 134,217,728
constexpr long ZN         = (long)BHn * CL;        // 65,536

// Scratch (static device globals -- no runtime allocation)
__device__ float  g_Q[PROJ_ELEMS];
__device__ float  g_K[PROJ_ELEMS];
__device__ float  g_V[PROJ_ELEMS];
__device__ __half g_E[S_ELEMS];                    // exp(scores), fp16
__device__ __half g_Vt[(long)BHn * CDK * CL];      // V transposed per (b,h): [64][2048]
__device__ float  g_Zp[16 * ZN];                   // per-ktile row-sum partials
__device__ float  g_invZ[ZN];

// ---------------------------------------------------------------------------
// helpers
// ---------------------------------------------------------------------------
__device__ __forceinline__ float f2tf(float x) {
    uint32_t r;
    asm("cvt.rna.tf32.f32 %0, %1;" : "=r"(r) : "f"(x));
    return __uint_as_float(r);
}

__device__ __forceinline__ void mma8(float* d, const uint32_t* a, const uint32_t* b) {
    asm volatile(
        "mma.sync.aligned.m16n8k8.row.col.f32.tf32.tf32.f32 "
        "{%0,%1,%2,%3}, {%4,%5,%6,%7}, {%8,%9}, {%0,%1,%2,%3};"
        : "+f"(d[0]), "+f"(d[1]), "+f"(d[2]), "+f"(d[3])
        : "r"(a[0]), "r"(a[1]), "r"(a[2]), "r"(a[3]), "r"(b[0]), "r"(b[1]));
}

__device__ __forceinline__ void mma16h(float* d, const uint32_t* a, const uint32_t* b) {
    asm volatile(
        "mma.sync.aligned.m16n8k16.row.col.f32.f16.f16.f32 "
        "{%0,%1,%2,%3}, {%4,%5,%6,%7}, {%8,%9}, {%0,%1,%2,%3};"
        : "+f"(d[0]), "+f"(d[1]), "+f"(d[2]), "+f"(d[3])
        : "r"(a[0]), "r"(a[1]), "r"(a[2]), "r"(a[3]), "r"(b[0]), "r"(b[1]));
}

// ---------------------------------------------------------------------------
// tf32 NT GEMM for projections: C[m,n] = sum_k A[m,k]*B[n,k]
// BM=64, BN=128, BK=16, 256 threads (2x4 warps).  (unchanged from round 3)
// ---------------------------------------------------------------------------
__global__ __launch_bounds__(256) void mma_gemm_nt(
    const float* __restrict__ A, const float* __restrict__ B, float* __restrict__ C,
    int K, int lda, int ldb, int ldc)
{
    __shared__ float As[64][20];
    __shared__ float Bs[128][20];

    const float* Ab = A + (long)blockIdx.y * 64 * lda;
    const float* Bb = B + (long)blockIdx.x * 128 * ldb;
    float* Cb = C + (long)blockIdx.y * 64 * ldc + (long)blockIdx.x * 128;

    const int tid  = threadIdx.x;
    const int w    = tid >> 5, lane = tid & 31;
    const int wm   = w >> 2, wn = w & 3;
    const int g    = lane >> 2, tig = lane & 3;

    float acc[2][4][4];
    #pragma unroll
    for (int i = 0; i < 2; i++)
        #pragma unroll
        for (int j = 0; j < 4; j++)
            #pragma unroll
            for (int r = 0; r < 4; r++) acc[i][j][r] = 0.f;

    float4 pa, pb[2];
    pa = *(const float4*)(Ab + (long)(tid >> 2) * lda + ((tid & 3) << 2));
    #pragma unroll
    for (int j = 0; j < 2; j++) {
        int f = tid + 256 * j;
        pb[j] = *(const float4*)(Bb + (long)(f >> 2) * ldb + ((f & 3) << 2));
    }

    for (int k0 = 0; k0 < K; k0 += 16) {
        {
            int r = tid >> 2, kq = (tid & 3) << 2;
            As[r][kq + 0] = f2tf(pa.x); As[r][kq + 1] = f2tf(pa.y);
            As[r][kq + 2] = f2tf(pa.z); As[r][kq + 3] = f2tf(pa.w);
        }
        #pragma unroll
        for (int j = 0; j < 2; j++) {
            int f = tid + 256 * j;
            int r = f >> 2, kq = (f & 3) << 2;
            Bs[r][kq + 0] = f2tf(pb[j].x); Bs[r][kq + 1] = f2tf(pb[j].y);
            Bs[r][kq + 2] = f2tf(pb[j].z); Bs[r][kq + 3] = f2tf(pb[j].w);
        }
        __syncthreads();

        if (k0 + 16 < K) {
            pa = *(const float4*)(Ab + (long)(tid >> 2) * lda + k0 + 16 + ((tid & 3) << 2));
            #pragma unroll
            for (int j = 0; j < 2; j++) {
                int f = tid + 256 * j;
                pb[j] = *(const float4*)(Bb + (long)(f >> 2) * ldb + k0 + 16 + ((f & 3) << 2));
            }
        }

        #pragma unroll
        for (int ks = 0; ks < 2; ks++) {
            const int c0 = ks * 8;
            uint32_t af[2][4], bf[4][2];
            #pragma unroll
            for (int mt = 0; mt < 2; mt++) {
                int r0 = wm * 32 + mt * 16 + g;
                af[mt][0] = __float_as_uint(As[r0][c0 + tig]);
                af[mt][1] = __float_as_uint(As[r0 + 8][c0 + tig]);
                af[mt][2] = __float_as_uint(As[r0][c0 + tig + 4]);
                af[mt][3] = __float_as_uint(As[r0 + 8][c0 + tig + 4]);
            }
            #pragma unroll
            for (int nt = 0; nt < 4; nt++) {
                int n = wn * 32 + nt * 8 + g;
                bf[nt][0] = __float_as_uint(Bs[n][c0 + tig]);
                bf[nt][1] = __float_as_uint(Bs[n][c0 + tig + 4]);
            }
            #pragma unroll
            for (int mt = 0; mt < 2; mt++)
                #pragma unroll
                for (int nt = 0; nt < 4; nt++)
                    mma8(acc[mt][nt], af[mt], bf[nt]);
        }
        __syncthreads();
    }

    #pragma unroll
    for (int mt = 0; mt < 2; mt++)
        #pragma unroll
        for (int nt = 0; nt < 4; nt++) {
            long r0  = wm * 32 + mt * 16 + g;
            int  col = wn * 32 + nt * 8 + 2 * tig;
            *(float2*)&Cb[r0 * ldc + col]       = make_float2(acc[mt][nt][0], acc[mt][nt][1]);
            *(float2*)&Cb[(r0 + 8) * ldc + col] = make_float2(acc[mt][nt][2], acc[mt][nt][3]);
        }
}

// ---------------------------------------------------------------------------
// L2 normalize each contiguous 64-float segment (one warp per segment).
// ---------------------------------------------------------------------------
__global__ __launch_bounds__(256) void l2norm_kernel(float* __restrict__ X, float coef)
{
    const int seg  = blockIdx.x * 8 + (threadIdx.x >> 5);
    const int lane = threadIdx.x & 31;
    float2* p = (float2*)(X + (long)seg * 64) + lane;
    float2 u = *p;
    float ss = u.x * u.x + u.y * u.y;
    #pragma unroll
    for (int o = 16; o; o >>= 1) ss += __shfl_xor_sync(0xffffffffu, ss, o);
    const float s = coef / fmaxf(sqrtf(ss), 1e-12f);
    u.x *= s; u.y *= s;
    *p = u;
}

// ---------------------------------------------------------------------------
// V transpose + fp16 convert: Vt[z][n][k] = half(V[b][k][h*64+n])
// grid: (CL/128, BHn), 256 threads.
// ---------------------------------------------------------------------------
__global__ __launch_bounds__(256) void vt_kernel(const float* __restrict__ V,
                                                 __half* __restrict__ Vt)
{
    __shared__ float sm[128][65];
    const int z = blockIdx.y, b = z >> 4, h = z & 15;
    const int k0 = blockIdx.x * 128;
    const float* Vb = V + ((long)b * CL + k0) * CD + h * 64;
    for (int i = threadIdx.x; i < 128 * 64; i += 256) {
        int kk = i >> 6, n = i & 63;
        sm[kk][n] = Vb[(long)kk * CD + n];
    }
    __syncthreads();
    __half* Ob = Vt + (long)z * CDK * CL + k0;
    for (int i = threadIdx.x; i < 64 * 128; i += 256) {
        int n = i >> 7, kk = i & 127;
        Ob[(long)n * CL + kk] = __float2half(sm[kk][n]);
    }
}

// ---------------------------------------------------------------------------
// Scores + exp: per (b,h): E[q,k] = exp(Qn[q,:].Kn[k,:]) (fp16) + per-row
// partial sums (deterministic shfl/smem reduction) to Zp[ktile].
// BM=64 (q), BN=128 (k), K=64. grid (16, 32, 32).
// ---------------------------------------------------------------------------
__global__ __launch_bounds__(256) void scores_exp_kernel(
    const float* __restrict__ Q, const float* __restrict__ Km,
    __half* __restrict__ E, float* __restrict__ Zp)
{
    __shared__ float As[64][20];
    __shared__ float Bs[128][20];
    __shared__ float zs[64][5];

    const int z = blockIdx.z, b = z >> 4, h = z & 15;
    const float* Ab = Q  + (long)b * CL * CD + h * 64 + (long)blockIdx.y * 64 * CD;
    const float* Bb = Km + (long)b * CL * CD + h * 64 + (long)blockIdx.x * 128 * CD;
    __half* Eb = E + (long)z * CL * CL + (long)blockIdx.y * 64 * CL + blockIdx.x * 128;

    const int tid  = threadIdx.x;
    const int w    = tid >> 5, lane = tid & 31;
    const int wm   = w >> 2, wn = w & 3;
    const int g    = lane >> 2, tig = lane & 3;

    float acc[2][4][4];
    #pragma unroll
    for (int i = 0; i < 2; i++)
        #pragma unroll
        for (int j = 0; j < 4; j++)
            #pragma unroll
            for (int r = 0; r < 4; r++) acc[i][j][r] = 0.f;

    float4 pa, pb[2];
    pa = *(const float4*)(Ab + (long)(tid >> 2) * CD + ((tid & 3) << 2));
    #pragma unroll
    for (int j = 0; j < 2; j++) {
        int f = tid + 256 * j;
        pb[j] = *(const float4*)(Bb + (long)(f >> 2) * CD + ((f & 3) << 2));
    }

    #pragma unroll
    for (int k0 = 0; k0 < 64; k0 += 16) {
        {
            int r = tid >> 2, kq = (tid & 3) << 2;
            As[r][kq + 0] = f2tf(pa.x); As[r][kq + 1] = f2tf(pa.y);
            As[r][kq + 2] = f2tf(pa.z); As[r][kq + 3] = f2tf(pa.w);
        }
        #pragma unroll
        for (int j = 0; j < 2; j++) {
            int f = tid + 256 * j;
            int r = f >> 2, kq = (f & 3) << 2;
            Bs[r][kq + 0] = f2tf(pb[j].x); Bs[r][kq + 1] = f2tf(pb[j].y);
            Bs[r][kq + 2] = f2tf(pb[j].z); Bs[r][kq + 3] = f2tf(pb[j].w);
        }
        __syncthreads();

        if (k0 + 16 < 64) {
            pa = *(const float4*)(Ab + (long)(tid >> 2) * CD + k0 + 16 + ((tid & 3) << 2));
            #pragma unroll
            for (int j = 0; j < 2; j++) {
                int f = tid + 256 * j;
                pb[j] = *(const float4*)(Bb + (long)(f >> 2) * CD + k0 + 16 + ((f & 3) << 2));
            }
        }

        #pragma unroll
        for (int ks = 0; ks < 2; ks++) {
            const int c0 = ks * 8;
            uint32_t af[2][4], bf[4][2];
            #pragma unroll
            for (int mt = 0; mt < 2; mt++) {
                int r0 = wm * 32 + mt * 16 + g;
                af[mt][0] = __float_as_uint(As[r0][c0 + tig]);
                af[mt][1] = __float_as_uint(As[r0 + 8][c0 + tig]);
                af[mt][2] = __float_as_uint(As[r0][c0 + tig + 4]);
                af[mt][3] = __float_as_uint(As[r0 + 8][c0 + tig + 4]);
            }
            #pragma unroll
            for (int nt = 0; nt < 4; nt++) {
                int n = wn * 32 + nt * 8 + g;
                bf[nt][0] = __float_as_uint(Bs[n][c0 + tig]);
                bf[nt][1] = __float_as_uint(Bs[n][c0 + tig + 4]);
            }
            #pragma unroll
            for (int mt = 0; mt < 2; mt++)
                #pragma unroll
                for (int nt = 0; nt < 4; nt++)
                    mma8(acc[mt][nt], af[mt], bf[nt]);
        }
        __syncthreads();
    }

    // epilogue: exp, fp16 write, deterministic row sums
    float rs[2][2] = {{0.f, 0.f}, {0.f, 0.f}};
    #pragma unroll
    for (int mt = 0; mt < 2; mt++) {
        long r0 = wm * 32 + mt * 16 + g;
        #pragma unroll
        for (int nt = 0; nt < 4; nt++) {
            int col = wn * 32 + nt * 8 + 2 * tig;
            float e0 = __expf(acc[mt][nt][0]);
            float e1 = __expf(acc[mt][nt][1]);
            float e2 = __expf(acc[mt][nt][2]);
            float e3 = __expf(acc[mt][nt][3]);
            *(__half2*)&Eb[r0 * CL + col]       = __floats2half2_rn(e0, e1);
            *(__half2*)&Eb[(r0 + 8) * CL + col] = __floats2half2_rn(e2, e3);
            rs[mt][0] += e0 + e1;
            rs[mt][1] += e2 + e3;
        }
    }
    #pragma unroll
    for (int mt = 0; mt < 2; mt++)
        #pragma unroll
        for (int o = 1; o <= 2; o <<= 1) {
            rs[mt][0] += __shfl_xor_sync(0xffffffffu, rs[mt][0], o);
            rs[mt][1] += __shfl_xor_sync(0xffffffffu, rs[mt][1], o);
        }
    if (tig == 0) {
        #pragma unroll
        for (int mt = 0; mt < 2; mt++) {
            zs[wm * 32 + mt * 16 + g][wn]     = rs[mt][0];
            zs[wm * 32 + mt * 16 + g + 8][wn] = rs[mt][1];
        }
    }
    __syncthreads();
    if (tid < 64) {
        float s = zs[tid][0] + zs[tid][1] + zs[tid][2] + zs[tid][3];
        Zp[(long)blockIdx.x * ZN + (long)z * CL + blockIdx.y * 64 + tid] = s;
    }
}

// ---------------------------------------------------------------------------
// invZ[i] = 1 / sum of the 16 k-tile partials (fixed order -> deterministic)
// ---------------------------------------------------------------------------
__global__ __launch_bounds__(256) void zreduce_kernel(const float* __restrict__ Zp,
                                                      float* __restrict__ invZ)
{
    const long i = (long)blockIdx.x * 256 + threadIdx.x;
    float s = 0.f;
    #pragma unroll
    for (int p = 0; p < 16; p++) s += Zp[(long)p * ZN + i];
    invZ[i] = 1.0f / s;
}

// ---------------------------------------------------------------------------
// PV fp16 NT GEMM: out[q,n] = invZ[q] * sum_k E[q,k] * Vt[n,k]
// BM=64, BN=64, BK=32, 256 threads. grid (1, 32, 32).
// ---------------------------------------------------------------------------
__global__ __launch_bounds__(256) void pv_kernel(
    const __half* __restrict__ E, const __half* __restrict__ Vt,
    const float* __restrict__ invZ, float* __restrict__ out)
{
    __shared__ __half As[64][40];
    __shared__ __half Bs[64][40];

    const int z = blockIdx.z;
    const __half* Ab = E  + (long)z * CL * CL + (long)blockIdx.y * 64 * CL;
    const __half* Bb = Vt + (long)z * CDK * CL;
    float* Cb = out + (long)z * CL * CDK + (long)blockIdx.y * 64 * CDK;

    const int tid  = threadIdx.x;
    const int w    = tid >> 5, lane = tid & 31;
    const int wm   = w >> 2, wn = w & 3;
    const int g    = lane >> 2, tig = lane & 3;
    const int lr   = tid >> 2;          // 0..63
    const int lkc  = (tid & 3) * 8;     // 0,8,16,24

    float acc[2][2][4];
    #pragma unroll
    for (int i = 0; i < 2; i++)
        #pragma unroll
        for (int j = 0; j < 2; j++)
            #pragma unroll
            for (int r = 0; r < 4; r++) acc[i][j][r] = 0.f;

    uint4 pa = *(const uint4*)(Ab + (long)lr * CL + lkc);
    uint4 pb = *(const uint4*)(Bb + (long)lr * CL + lkc);

    for (int k0 = 0; k0 < CL; k0 += 32) {
        *(uint4*)&As[lr][lkc] = pa;
        *(uint4*)&Bs[lr][lkc] = pb;
        __syncthreads();

        if (k0 + 32 < CL) {
            pa = *(const uint4*)(Ab + (long)lr * CL + k0 + 32 + lkc);
            pb = *(const uint4*)(Bb + (long)lr * CL + k0 + 32 + lkc);
        }

        #pragma unroll
        for (int ks = 0; ks < 2; ks++) {
            const int c0 = ks * 16;
            uint32_t af[2][4], bf[2][2];
            #pragma unroll
            for (int mt = 0; mt < 2; mt++) {
                int r0 = wm * 32 + mt * 16 + g;
                af[mt][0] = *(const uint32_t*)&As[r0][c0 + 2 * tig];
                af[mt][1] = *(const uint32_t*)&As[r0 + 8][c0 + 2 * tig];
                af[mt][2] = *(const uint32_t*)&As[r0][c0 + 2 * tig + 8];
                af[mt][3] = *(const uint32_t*)&As[r0 + 8][c0 + 2 * tig + 8];
            }
            #pragma unroll
            for (int nt = 0; nt < 2; nt++) {
                int n = wn * 16 + nt * 8 + g;
                bf[nt][0] = *(const uint32_t*)&Bs[n][c0 + 2 * tig];
                bf[nt][1] = *(const uint32_t*)&Bs[n][c0 + 2 * tig + 8];
            }
            #pragma unroll
            for (int mt = 0; mt < 2; mt++)
                #pragma unroll
                for (int nt = 0; nt < 2; nt++)
                    mma16h(acc[mt][nt], af[mt], bf[nt]);
        }
        __syncthreads();
    }

    const float* izb = invZ + (long)z * CL + blockIdx.y * 64;
    #pragma unroll
    for (int mt = 0; mt < 2; mt++) {
        long r0 = wm * 32 + mt * 16 + g;
        float i0 = izb[r0], i1 = izb[r0 + 8];
        #pragma unroll
        for (int nt = 0; nt < 2; nt++) {
            int col = wn * 16 + nt * 8 + 2 * tig;
            *(float2*)&Cb[r0 * CDK + col]       = make_float2(acc[mt][nt][0] * i0,
                                                              acc[mt][nt][1] * i0);
            *(float2*)&Cb[(r0 + 8) * CDK + col] = make_float2(acc[mt][nt][2] * i1,
                                                              acc[mt][nt][3] * i1);
        }
    }
}

// ---------------------------------------------------------------------------
// avg[b,q,k] = (1/16) * sum_h E[b,h,q,k] * invZ[b,h,q].  Block per (b,q).
// ---------------------------------------------------------------------------
__global__ __launch_bounds__(256) void avg_kernel(const __half* __restrict__ E,
                                                  const float* __restrict__ invZ,
                                                  float* __restrict__ avg)
{
    const int b = blockIdx.x >> 11, q = blockIdx.x & 2047;
    const int t = threadIdx.x;
    __shared__ float wz[16];
    if (t < 16)
        wz[t] = invZ[(long)(b * 16 + t) * CL + q] * (1.0f / 16.0f);
    __syncthreads();

    float2 a[4];
    #pragma unroll
    for (int i = 0; i < 4; i++) a[i] = make_float2(0.f, 0.f);

    #pragma unroll
    for (int h = 0; h < 16; h++) {
        const __half2* row = (const __half2*)(E + ((long)(b * 16 + h) * CL + q) * CL);
        const float wh = wz[h];
        #pragma unroll
        for (int i = 0; i < 4; i++) {
            float2 f = __half22float2(row[t + 256 * i]);
            a[i].x += wh * f.x;
            a[i].y += wh * f.y;
        }
    }
    float2* arow = (float2*)(avg + ((long)b * CL + q) * CL);
    #pragma unroll
    for (int i = 0; i < 4; i++) arow[t + 256 * i] = a[i];
}

// ---------------------------------------------------------------------------
extern "C" void kernel_launch(void* const* d_in, const int* in_sizes, int n_in,
                              void* d_out, int out_size)
{
    const float* q  = (const float*)d_in[0];
    const float* k  = (const float*)d_in[1];
    const float* v  = (const float*)d_in[2];
    const float* wq = (const float*)d_in[3];
    const float* wk = (const float*)d_in[4];
    const float* wv = (const float*)d_in[5];

    float* out = (float*)d_out;                        // [B,H,L,64]
    float* avg = out + (long)CB * CH * CL * CDK;       // [B,L,L]

    float *Qp, *Kp, *Vp, *Zp, *iZ;
    __half *Ep, *Vtp;
    cudaGetSymbolAddress((void**)&Qp,  g_Q);
    cudaGetSymbolAddress((void**)&Kp,  g_K);
    cudaGetSymbolAddress((void**)&Vp,  g_V);
    cudaGetSymbolAddress((void**)&Ep,  g_E);
    cudaGetSymbolAddress((void**)&Vtp, g_Vt);
    cudaGetSymbolAddress((void**)&Zp,  g_Zp);
    cudaGetSymbolAddress((void**)&iZ,  g_invZ);

    // 1) Projections (tf32 MMA): [4096,1024] x [1024,1024]^T
    dim3 pg(CD / 128, (CB * CL) / 64, 1);
    mma_gemm_nt<<<pg, 256>>>(q, wq, Qp, CD, CD, CD, CD);
    mma_gemm_nt<<<pg, 256>>>(k, wk, Kp, CD, CD, CD, CD);
    mma_gemm_nt<<<pg, 256>>>(v, wv, Vp, CD, CD, CD, CD);

    // 2) L2 normalize Q,K (fold 1/8 into Q); transpose+convert V to fp16
    l2norm_kernel<<<(CB * CL * CH) / 8, 256>>>(Qp, 0.125f);
    l2norm_kernel<<<(CB * CL * CH) / 8, 256>>>(Kp, 1.0f);
    dim3 vg(CL / 128, BHn);
    vt_kernel<<<vg, 256>>>(Vp, Vtp);

    // 3) E = exp(scores) fp16 + row-sum partials
    dim3 sg(CL / 128, CL / 64, BHn);
    scores_exp_kernel<<<sg, 256>>>(Qp, Kp, Ep, Zp);

    // 4) invZ
    zreduce_kernel<<<ZN / 256, 256>>>(Zp, iZ);

    // 5) out = (E @ V) * invZ   (fp16 MMA, NT vs V^T)
    dim3 og(1, CL / 64, BHn);
    pv_kernel<<<og, 256>>>(Ep, Vtp, iZ, out);

    // 6) attn_avg
    avg_kernel<<<CB * CL, 256>>>(Ep, iZ, avg);
}

// round 5
// speedup vs baseline: 2.6833x; 1.1679x over previous
#include <cuda_runtime.h>
#include <cuda_fp16.h>
#include <stdint.h>

// Problem constants
#define CB 2
#define CL 2048
#define CD 1024
#define CH 16
#define CDK 64

constexpr int  BHn        = CB * CH;               // 32
constexpr long PROJ_ELEMS = (long)CB * CL * CD;    // 4,194,304
constexpr long S_ELEMS    = (long)BHn * CL * CL;   // 134,217,728
constexpr long ZN         = (long)BHn * CL;        // 65,536

// Scratch (static device globals -- no runtime allocation)
__device__ float  g_Q[PROJ_ELEMS];
__device__ float  g_K[PROJ_ELEMS];
__device__ float  g_V[PROJ_ELEMS];
__device__ __half g_Qh[PROJ_ELEMS];                // normalized Q, fp16
__device__ __half g_Kh[PROJ_ELEMS];                // normalized K, fp16
__device__ __half g_E[S_ELEMS];                    // exp(scores), fp16
__device__ __half g_Vt[(long)BHn * CDK * CL];      // V^T per (b,h): [64][2048]
__device__ float  g_Zp[16 * ZN];                   // per-ktile row-sum partials
__device__ float  g_invZ[ZN];

// ---------------------------------------------------------------------------
// helpers
// ---------------------------------------------------------------------------
__device__ __forceinline__ float f2tf(float x) {
    uint32_t r;
    asm("cvt.rna.tf32.f32 %0, %1;" : "=r"(r) : "f"(x));
    return __uint_as_float(r);
}

__device__ __forceinline__ void mma8(float* d, const uint32_t* a, const uint32_t* b) {
    asm volatile(
        "mma.sync.aligned.m16n8k8.row.col.f32.tf32.tf32.f32 "
        "{%0,%1,%2,%3}, {%4,%5,%6,%7}, {%8,%9}, {%0,%1,%2,%3};"
        : "+f"(d[0]), "+f"(d[1]), "+f"(d[2]), "+f"(d[3])
        : "r"(a[0]), "r"(a[1]), "r"(a[2]), "r"(a[3]), "r"(b[0]), "r"(b[1]));
}

__device__ __forceinline__ void mma16h(float* d, const uint32_t* a, const uint32_t* b) {
    asm volatile(
        "mma.sync.aligned.m16n8k16.row.col.f32.f16.f16.f32 "
        "{%0,%1,%2,%3}, {%4,%5,%6,%7}, {%8,%9}, {%0,%1,%2,%3};"
        : "+f"(d[0]), "+f"(d[1]), "+f"(d[2]), "+f"(d[3])
        : "r"(a[0]), "r"(a[1]), "r"(a[2]), "r"(a[3]), "r"(b[0]), "r"(b[1]));
}

__device__ __forceinline__ uint32_t sptr(const void* p) {
    return (uint32_t)__cvta_generic_to_shared(p);
}

__device__ __forceinline__ void ldmA(uint32_t* a, uint32_t addr) {
    asm volatile("ldmatrix.sync.aligned.m8n8.x4.shared.b16 {%0,%1,%2,%3}, [%4];"
                 : "=r"(a[0]), "=r"(a[1]), "=r"(a[2]), "=r"(a[3]) : "r"(addr));
}

__device__ __forceinline__ void ldmB(uint32_t* b, uint32_t addr) {
    asm volatile("ldmatrix.sync.aligned.m8n8.x2.shared.b16 {%0,%1}, [%2];"
                 : "=r"(b[0]), "=r"(b[1]) : "r"(addr));
}

// ---------------------------------------------------------------------------
// tf32 NT GEMM for projections: C[m,n] = sum_k A[m,k]*B[n,k]
// BM=64, BN=128, BK=16, 256 threads (2x4 warps).
// ---------------------------------------------------------------------------
__global__ __launch_bounds__(256) void mma_gemm_nt(
    const float* __restrict__ A, const float* __restrict__ B, float* __restrict__ C,
    int K, int lda, int ldb, int ldc)
{
    __shared__ float As[64][20];
    __shared__ float Bs[128][20];

    const float* Ab = A + (long)blockIdx.y * 64 * lda;
    const float* Bb = B + (long)blockIdx.x * 128 * ldb;
    float* Cb = C + (long)blockIdx.y * 64 * ldc + (long)blockIdx.x * 128;

    const int tid  = threadIdx.x;
    const int w    = tid >> 5, lane = tid & 31;
    const int wm   = w >> 2, wn = w & 3;
    const int g    = lane >> 2, tig = lane & 3;

    float acc[2][4][4];
    #pragma unroll
    for (int i = 0; i < 2; i++)
        #pragma unroll
        for (int j = 0; j < 4; j++)
            #pragma unroll
            for (int r = 0; r < 4; r++) acc[i][j][r] = 0.f;

    float4 pa, pb[2];
    pa = *(const float4*)(Ab + (long)(tid >> 2) * lda + ((tid & 3) << 2));
    #pragma unroll
    for (int j = 0; j < 2; j++) {
        int f = tid + 256 * j;
        pb[j] = *(const float4*)(Bb + (long)(f >> 2) * ldb + ((f & 3) << 2));
    }

    for (int k0 = 0; k0 < K; k0 += 16) {
        {
            int r = tid >> 2, kq = (tid & 3) << 2;
            As[r][kq + 0] = f2tf(pa.x); As[r][kq + 1] = f2tf(pa.y);
            As[r][kq + 2] = f2tf(pa.z); As[r][kq + 3] = f2tf(pa.w);
        }
        #pragma unroll
        for (int j = 0; j < 2; j++) {
            int f = tid + 256 * j;
            int r = f >> 2, kq = (f & 3) << 2;
            Bs[r][kq + 0] = f2tf(pb[j].x); Bs[r][kq + 1] = f2tf(pb[j].y);
            Bs[r][kq + 2] = f2tf(pb[j].z); Bs[r][kq + 3] = f2tf(pb[j].w);
        }
        __syncthreads();

        if (k0 + 16 < K) {
            pa = *(const float4*)(Ab + (long)(tid >> 2) * lda + k0 + 16 + ((tid & 3) << 2));
            #pragma unroll
            for (int j = 0; j < 2; j++) {
                int f = tid + 256 * j;
                pb[j] = *(const float4*)(Bb + (long)(f >> 2) * ldb + k0 + 16 + ((f & 3) << 2));
            }
        }

        #pragma unroll
        for (int ks = 0; ks < 2; ks++) {
            const int c0 = ks * 8;
            uint32_t af[2][4], bf[4][2];
            #pragma unroll
            for (int mt = 0; mt < 2; mt++) {
                int r0 = wm * 32 + mt * 16 + g;
                af[mt][0] = __float_as_uint(As[r0][c0 + tig]);
                af[mt][1] = __float_as_uint(As[r0 + 8][c0 + tig]);
                af[mt][2] = __float_as_uint(As[r0][c0 + tig + 4]);
                af[mt][3] = __float_as_uint(As[r0 + 8][c0 + tig + 4]);
            }
            #pragma unroll
            for (int nt = 0; nt < 4; nt++) {
                int n = wn * 32 + nt * 8 + g;
                bf[nt][0] = __float_as_uint(Bs[n][c0 + tig]);
                bf[nt][1] = __float_as_uint(Bs[n][c0 + tig + 4]);
            }
            #pragma unroll
            for (int mt = 0; mt < 2; mt++)
                #pragma unroll
                for (int nt = 0; nt < 4; nt++)
                    mma8(acc[mt][nt], af[mt], bf[nt]);
        }
        __syncthreads();
    }

    #pragma unroll
    for (int mt = 0; mt < 2; mt++)
        #pragma unroll
        for (int nt = 0; nt < 4; nt++) {
            long r0  = wm * 32 + mt * 16 + g;
            int  col = wn * 32 + nt * 8 + 2 * tig;
            *(float2*)&Cb[r0 * ldc + col]       = make_float2(acc[mt][nt][0], acc[mt][nt][1]);
            *(float2*)&Cb[(r0 + 8) * ldc + col] = make_float2(acc[mt][nt][2], acc[mt][nt][3]);
        }
}

// ---------------------------------------------------------------------------
// L2 normalize each 64-float segment and emit fp16 (one warp per segment).
// ---------------------------------------------------------------------------
__global__ __launch_bounds__(256) void l2norm_h_kernel(const float* __restrict__ X,
                                                       __half* __restrict__ Y, float coef)
{
    const int seg  = blockIdx.x * 8 + (threadIdx.x >> 5);
    const int lane = threadIdx.x & 31;
    float2 u = *((const float2*)(X + (long)seg * 64) + lane);
    float ss = u.x * u.x + u.y * u.y;
    #pragma unroll
    for (int o = 16; o; o >>= 1) ss += __shfl_xor_sync(0xffffffffu, ss, o);
    const float s = coef / fmaxf(sqrtf(ss), 1e-12f);
    *((__half2*)(Y + (long)seg * 64) + lane) = __floats2half2_rn(u.x * s, u.y * s);
}

// ---------------------------------------------------------------------------
// V transpose + fp16 convert: Vt[z][n][k] = half(V[b][k][h*64+n])
// ---------------------------------------------------------------------------
__global__ __launch_bounds__(256) void vt_kernel(const float* __restrict__ V,
                                                 __half* __restrict__ Vt)
{
    __shared__ float sm[128][65];
    const int z = blockIdx.y, b = z >> 4, h = z & 15;
    const int k0 = blockIdx.x * 128;
    const float* Vb = V + ((long)b * CL + k0) * CD + h * 64;
    for (int i = threadIdx.x; i < 128 * 64; i += 256) {
        int kk = i >> 6, n = i & 63;
        sm[kk][n] = Vb[(long)kk * CD + n];
    }
    __syncthreads();
    __half* Ob = Vt + (long)z * CDK * CL + k0;
    for (int i = threadIdx.x; i < 64 * 128; i += 256) {
        int n = i >> 7, kk = i & 127;
        Ob[(long)n * CL + kk] = __float2half(sm[kk][n]);
    }
}

// ---------------------------------------------------------------------------
// Scores + exp (fp16 MMA, single K=64 stage, ldmatrix fragments):
// E[q,k] = exp(Qh[q,:].Kh[k,:]) fp16, plus per-row k-tile partial sums.
// BM=64 (q), BN=128 (k). grid (16, 32, 32), 256 threads.
// ---------------------------------------------------------------------------
__global__ __launch_bounds__(256) void scores_exp_kernel(
    const __half* __restrict__ Qh, const __half* __restrict__ Kh,
    __half* __restrict__ E, float* __restrict__ Zp)
{
    __shared__ __half As[64][72];
    __shared__ __half Bs[128][72];
    __shared__ float  zs[64][5];

    const int z = blockIdx.z, b = z >> 4, h = z & 15;
    const __half* Ab = Qh + (long)b * CL * CD + h * 64 + (long)blockIdx.y * 64 * CD;
    const __half* Bb = Kh + (long)b * CL * CD + h * 64 + (long)blockIdx.x * 128 * CD;
    __half* Eb = E + (long)z * CL * CL + (long)blockIdx.y * 64 * CL + blockIdx.x * 128;

    const int tid  = threadIdx.x;
    const int w    = tid >> 5, lane = tid & 31;
    const int wm   = w >> 2, wn = w & 3;
    const int g    = lane >> 2, tig = lane & 3;

    // stage tiles (uint4 = 8 halves)
    #pragma unroll
    for (int j = 0; j < 2; j++) {
        int f = tid + 256 * j;
        int r = f >> 3, c = (f & 7) * 8;
        *(uint4*)&As[r][c] = *(const uint4*)(Ab + (long)r * CD + c);
    }
    #pragma unroll
    for (int j = 0; j < 4; j++) {
        int f = tid + 256 * j;
        int r = f >> 3, c = (f & 7) * 8;
        *(uint4*)&Bs[r][c] = *(const uint4*)(Bb + (long)r * CD + c);
    }
    __syncthreads();

    float acc[2][4][4];
    #pragma unroll
    for (int i = 0; i < 2; i++)
        #pragma unroll
        for (int j = 0; j < 4; j++)
            #pragma unroll
            for (int r = 0; r < 4; r++) acc[i][j][r] = 0.f;

    #pragma unroll
    for (int ks = 0; ks < 4; ks++) {
        const int c0 = ks * 16;
        uint32_t af[2][4], bf[4][2];
        #pragma unroll
        for (int mt = 0; mt < 2; mt++)
            ldmA(af[mt], sptr(&As[wm * 32 + mt * 16 + (lane & 15)][c0 + (lane >> 4) * 8]));
        #pragma unroll
        for (int nt = 0; nt < 4; nt++)
            ldmB(bf[nt], sptr(&Bs[wn * 32 + nt * 8 + (lane & 7)][c0 + ((lane >> 3) & 1) * 8]));
        #pragma unroll
        for (int mt = 0; mt < 2; mt++)
            #pragma unroll
            for (int nt = 0; nt < 4; nt++)
                mma16h(acc[mt][nt], af[mt], bf[nt]);
    }

    // epilogue: exp, fp16 write, deterministic row sums
    float rs[2][2] = {{0.f, 0.f}, {0.f, 0.f}};
    #pragma unroll
    for (int mt = 0; mt < 2; mt++) {
        long r0 = wm * 32 + mt * 16 + g;
        #pragma unroll
        for (int nt = 0; nt < 4; nt++) {
            int col = wn * 32 + nt * 8 + 2 * tig;
            float e0 = __expf(acc[mt][nt][0]);
            float e1 = __expf(acc[mt][nt][1]);
            float e2 = __expf(acc[mt][nt][2]);
            float e3 = __expf(acc[mt][nt][3]);
            *(__half2*)&Eb[r0 * CL + col]       = __floats2half2_rn(e0, e1);
            *(__half2*)&Eb[(r0 + 8) * CL + col] = __floats2half2_rn(e2, e3);
            rs[mt][0] += e0 + e1;
            rs[mt][1] += e2 + e3;
        }
    }
    #pragma unroll
    for (int mt = 0; mt < 2; mt++)
        #pragma unroll
        for (int o = 1; o <= 2; o <<= 1) {
            rs[mt][0] += __shfl_xor_sync(0xffffffffu, rs[mt][0], o);
            rs[mt][1] += __shfl_xor_sync(0xffffffffu, rs[mt][1], o);
        }
    if (tig == 0) {
        #pragma unroll
        for (int mt = 0; mt < 2; mt++) {
            zs[wm * 32 + mt * 16 + g][wn]     = rs[mt][0];
            zs[wm * 32 + mt * 16 + g + 8][wn] = rs[mt][1];
        }
    }
    __syncthreads();
    if (tid < 64) {
        float s = zs[tid][0] + zs[tid][1] + zs[tid][2] + zs[tid][3];
        Zp[(long)blockIdx.x * ZN + (long)z * CL + blockIdx.y * 64 + tid] = s;
    }
}

// ---------------------------------------------------------------------------
// invZ[i] = 1 / sum of the 16 k-tile partials (fixed order -> deterministic)
// ---------------------------------------------------------------------------
__global__ __launch_bounds__(256) void zreduce_kernel(const float* __restrict__ Zp,
                                                      float* __restrict__ invZ)
{
    const long i = (long)blockIdx.x * 256 + threadIdx.x;
    float s = 0.f;
    #pragma unroll
    for (int p = 0; p < 16; p++) s += Zp[(long)p * ZN + i];
    invZ[i] = 1.0f / s;
}

// ---------------------------------------------------------------------------
// PV fp16 NT GEMM (ldmatrix): out[q,n] = invZ[q] * sum_k E[q,k] * Vt[n,k]
// BM=64, BN=64, BK=64, 256 threads. grid (1, 32, 32).
// ---------------------------------------------------------------------------
__global__ __launch_bounds__(256) void pv_kernel(
    const __half* __restrict__ E, const __half* __restrict__ Vt,
    const float* __restrict__ invZ, float* __restrict__ out)
{
    __shared__ __half As[64][72];
    __shared__ __half Bs[64][72];

    const int z = blockIdx.z;
    const __half* Ab = E  + (long)z * CL * CL + (long)blockIdx.y * 64 * CL;
    const __half* Bb = Vt + (long)z * CDK * CL;
    float* Cb = out + (long)z * CL * CDK + (long)blockIdx.y * 64 * CDK;

    const int tid  = threadIdx.x;
    const int w    = tid >> 5, lane = tid & 31;
    const int wm   = w >> 2, wn = w & 3;
    const int g    = lane >> 2, tig = lane & 3;
    const int lr   = tid >> 3;         // 0..31 (row pairs via 2 loads)
    const int lc   = (tid & 7) * 8;    // half offset

    float acc[2][2][4];
    #pragma unroll
    for (int i = 0; i < 2; i++)
        #pragma unroll
        for (int j = 0; j < 2; j++)
            #pragma unroll
            for (int r = 0; r < 4; r++) acc[i][j][r] = 0.f;

    uint4 pa[2], pb[2];
    #pragma unroll
    for (int j = 0; j < 2; j++) {
        int r = lr + 32 * j;
        pa[j] = *(const uint4*)(Ab + (long)r * CL + lc);
        pb[j] = *(const uint4*)(Bb + (long)r * CL + lc);
    }

    for (int k0 = 0; k0 < CL; k0 += 64) {
        #pragma unroll
        for (int j = 0; j < 2; j++) {
            int r = lr + 32 * j;
            *(uint4*)&As[r][lc] = pa[j];
            *(uint4*)&Bs[r][lc] = pb[j];
        }
        __syncthreads();

        if (k0 + 64 < CL) {
            #pragma unroll
            for (int j = 0; j < 2; j++) {
                int r = lr + 32 * j;
                pa[j] = *(const uint4*)(Ab + (long)r * CL + k0 + 64 + lc);
                pb[j] = *(const uint4*)(Bb + (long)r * CL + k0 + 64 + lc);
            }
        }

        #pragma unroll
        for (int ks = 0; ks < 4; ks++) {
            const int c0 = ks * 16;
            uint32_t af[2][4], bf[2][2];
            #pragma unroll
            for (int mt = 0; mt < 2; mt++)
                ldmA(af[mt], sptr(&As[wm * 32 + mt * 16 + (lane & 15)][c0 + (lane >> 4) * 8]));
            #pragma unroll
            for (int nt = 0; nt < 2; nt++)
                ldmB(bf[nt], sptr(&Bs[wn * 16 + nt * 8 + (lane & 7)][c0 + ((lane >> 3) & 1) * 8]));
            #pragma unroll
            for (int mt = 0; mt < 2; mt++)
                #pragma unroll
                for (int nt = 0; nt < 2; nt++)
                    mma16h(acc[mt][nt], af[mt], bf[nt]);
        }
        __syncthreads();
    }

    const float* izb = invZ + (long)z * CL + blockIdx.y * 64;
    #pragma unroll
    for (int mt = 0; mt < 2; mt++) {
        long r0 = wm * 32 + mt * 16 + g;
        float i0 = izb[r0], i1 = izb[r0 + 8];
        #pragma unroll
        for (int nt = 0; nt < 2; nt++) {
            int col = wn * 16 + nt * 8 + 2 * tig;
            *(float2*)&Cb[r0 * CDK + col]       = make_float2(acc[mt][nt][0] * i0,
                                                              acc[mt][nt][1] * i0);
            *(float2*)&Cb[(r0 + 8) * CDK + col] = make_float2(acc[mt][nt][2] * i1,
                                                              acc[mt][nt][3] * i1);
        }
    }
}

// ---------------------------------------------------------------------------
// avg[b,q,k] = (1/16) * sum_h E[b,h,q,k] * invZ[b,h,q].  Block per (b,q).
// ---------------------------------------------------------------------------
__global__ __launch_bounds__(256) void avg_kernel(const __half* __restrict__ E,
                                                  const float* __restrict__ invZ,
                                                  float* __restrict__ avg)
{
    const int b = blockIdx.x >> 11, q = blockIdx.x & 2047;
    const int t = threadIdx.x;
    __shared__ float wz[16];
    if (t < 16)
        wz[t] = invZ[(long)(b * 16 + t) * CL + q] * (1.0f / 16.0f);
    __syncthreads();

    float2 a[4];
    #pragma unroll
    for (int i = 0; i < 4; i++) a[i] = make_float2(0.f, 0.f);

    #pragma unroll
    for (int h = 0; h < 16; h++) {
        const __half2* row = (const __half2*)(E + ((long)(b * 16 + h) * CL + q) * CL);
        const float wh = wz[h];
        #pragma unroll
        for (int i = 0; i < 4; i++) {
            float2 f = __half22float2(row[t + 256 * i]);
            a[i].x += wh * f.x;
            a[i].y += wh * f.y;
        }
    }
    float2* arow = (float2*)(avg + ((long)b * CL + q) * CL);
    #pragma unroll
    for (int i = 0; i < 4; i++) arow[t + 256 * i] = a[i];
}

// ---------------------------------------------------------------------------
extern "C" void kernel_launch(void* const* d_in, const int* in_sizes, int n_in,
                              void* d_out, int out_size)
{
    const float* q  = (const float*)d_in[0];
    const float* k  = (const float*)d_in[1];
    const float* v  = (const float*)d_in[2];
    const float* wq = (const float*)d_in[3];
    const float* wk = (const float*)d_in[4];
    const float* wv = (const float*)d_in[5];

    float* out = (float*)d_out;                        // [B,H,L,64]
    float* avg = out + (long)CB * CH * CL * CDK;       // [B,L,L]

    float *Qp, *Kp, *Vp, *Zp, *iZ;
    __half *Qh, *Kh, *Ep, *Vtp;
    cudaGetSymbolAddress((void**)&Qp,  g_Q);
    cudaGetSymbolAddress((void**)&Kp,  g_K);
    cudaGetSymbolAddress((void**)&Vp,  g_V);
    cudaGetSymbolAddress((void**)&Qh,  g_Qh);
    cudaGetSymbolAddress((void**)&Kh,  g_Kh);
    cudaGetSymbolAddress((void**)&Ep,  g_E);
    cudaGetSymbolAddress((void**)&Vtp, g_Vt);
    cudaGetSymbolAddress((void**)&Zp,  g_Zp);
    cudaGetSymbolAddress((void**)&iZ,  g_invZ);

    // 1) Projections (tf32 MMA)
    dim3 pg(CD / 128, (CB * CL) / 64, 1);
    mma_gemm_nt<<<pg, 256>>>(q, wq, Qp, CD, CD, CD, CD);
    mma_gemm_nt<<<pg, 256>>>(k, wk, Kp, CD, CD, CD, CD);
    mma_gemm_nt<<<pg, 256>>>(v, wv, Vp, CD, CD, CD, CD);

    // 2) L2 normalize -> fp16 (fold 1/8 into Q); transpose+convert V to fp16
    l2norm_h_kernel<<<(CB * CL * CH) / 8, 256>>>(Qp, Qh, 0.125f);
    l2norm_h_kernel<<<(CB * CL * CH) / 8, 256>>>(Kp, Kh, 1.0f);
    dim3 vg(CL / 128, BHn);
    vt_kernel<<<vg, 256>>>(Vp, Vtp);

    // 3) E = exp(scores) fp16 + row-sum partials (fp16 MMA + ldmatrix)
    dim3 sg(CL / 128, CL / 64, BHn);
    scores_exp_kernel<<<sg, 256>>>(Qh, Kh, Ep, Zp);

    // 4) invZ
    zreduce_kernel<<<ZN / 256, 256>>>(Zp, iZ);

    // 5) out = (E @ V) * invZ   (fp16 MMA + ldmatrix)
    dim3 og(1, CL / 64, BHn);
    pv_kernel<<<og, 256>>>(Ep, Vtp, iZ, out);

    // 6) attn_avg
    avg_kernel<<<CB * CL, 256>>>(Ep, iZ, avg);
}

// round 7
// speedup vs baseline: 3.0774x; 1.1469x over previous
#include <cuda_runtime.h>
#include <cuda_fp16.h>
#include <stdint.h>

// Problem constants
#define CB 2
#define CL 2048
#define CD 1024
#define CH 16
#define CDK 64

constexpr int  BHn        = CB * CH;               // 32
constexpr long PROJ_ELEMS = (long)CB * CL * CD;    // 4,194,304
constexpr long S_ELEMS    = (long)BHn * CL * CL;   // 134,217,728
constexpr long ZN         = (long)BHn * CL;        // 65,536

// Scratch (static device globals -- no runtime allocation)
__device__ float  g_Q[PROJ_ELEMS];                 // Q projection, fp32
__device__ float  g_K[PROJ_ELEMS];                 // K projection, fp32
__device__ __half g_Qh[PROJ_ELEMS];                // normalized Q, fp16
__device__ __half g_Kh[PROJ_ELEMS];                // normalized K, fp16
__device__ __half g_Vh[PROJ_ELEMS];                // V projection, fp16 (natural layout)
__device__ __half g_E[S_ELEMS];                    // exp(scores), fp16
__device__ float  g_invZ[ZN];

// ---------------------------------------------------------------------------
// helpers
// ---------------------------------------------------------------------------
__device__ __forceinline__ float f2tf(float x) {
    uint32_t r;
    asm("cvt.rna.tf32.f32 %0, %1;" : "=r"(r) : "f"(x));
    return __uint_as_float(r);
}

__device__ __forceinline__ void mma8(float* d, const uint32_t* a, const uint32_t* b) {
    asm volatile(
        "mma.sync.aligned.m16n8k8.row.col.f32.tf32.tf32.f32 "
        "{%0,%1,%2,%3}, {%4,%5,%6,%7}, {%8,%9}, {%0,%1,%2,%3};"
        : "+f"(d[0]), "+f"(d[1]), "+f"(d[2]), "+f"(d[3])
        : "r"(a[0]), "r"(a[1]), "r"(a[2]), "r"(a[3]), "r"(b[0]), "r"(b[1]));
}

__device__ __forceinline__ void mma16h(float* d, const uint32_t* a, const uint32_t* b) {
    asm volatile(
        "mma.sync.aligned.m16n8k16.row.col.f32.f16.f16.f32 "
        "{%0,%1,%2,%3}, {%4,%5,%6,%7}, {%8,%9}, {%0,%1,%2,%3};"
        : "+f"(d[0]), "+f"(d[1]), "+f"(d[2]), "+f"(d[3])
        : "r"(a[0]), "r"(a[1]), "r"(a[2]), "r"(a[3]), "r"(b[0]), "r"(b[1]));
}

__device__ __forceinline__ uint32_t sptr(const void* p) {
    return (uint32_t)__cvta_generic_to_shared(p);
}

__device__ __forceinline__ void ldm4(uint32_t* a, uint32_t addr) {
    asm volatile("ldmatrix.sync.aligned.m8n8.x4.shared.b16 {%0,%1,%2,%3}, [%4];"
                 : "=r"(a[0]), "=r"(a[1]), "=r"(a[2]), "=r"(a[3]) : "r"(addr));
}

__device__ __forceinline__ void ldm4t(uint32_t* a, uint32_t addr) {
    asm volatile("ldmatrix.sync.aligned.m8n8.x4.trans.shared.b16 {%0,%1,%2,%3}, [%4];"
                 : "=r"(a[0]), "=r"(a[1]), "=r"(a[2]), "=r"(a[3]) : "r"(addr));
}

// ---------------------------------------------------------------------------
// tf32 NT GEMM for projections: C[m,n] = sum_k A[m,k]*B[n,k]
// BM=64, BN=128, BK=16, 256 threads (2x4 warps).
// HOUT=true writes fp16 output instead of fp32.
// ---------------------------------------------------------------------------
template<bool HOUT>
__global__ __launch_bounds__(256) void mma_gemm_nt(
    const float* __restrict__ A, const float* __restrict__ B,
    float* __restrict__ C, __half* __restrict__ Ch,
    int K, int lda, int ldb, int ldc)
{
    __shared__ float As[64][20];
    __shared__ float Bs[128][20];

    const float* Ab = A + (long)blockIdx.y * 64 * lda;
    const float* Bb = B + (long)blockIdx.x * 128 * ldb;

    const int tid  = threadIdx.x;
    const int w    = tid >> 5, lane = tid & 31;
    const int wm   = w >> 2, wn = w & 3;
    const int g    = lane >> 2, tig = lane & 3;

    float acc[2][4][4];
    #pragma unroll
    for (int i = 0; i < 2; i++)
        #pragma unroll
        for (int j = 0; j < 4; j++)
            #pragma unroll
            for (int r = 0; r < 4; r++) acc[i][j][r] = 0.f;

    float4 pa, pb[2];
    pa = *(const float4*)(Ab + (long)(tid >> 2) * lda + ((tid & 3) << 2));
    #pragma unroll
    for (int j = 0; j < 2; j++) {
        int f = tid + 256 * j;
        pb[j] = *(const float4*)(Bb + (long)(f >> 2) * ldb + ((f & 3) << 2));
    }

    for (int k0 = 0; k0 < K; k0 += 16) {
        {
            int r = tid >> 2, kq = (tid & 3) << 2;
            As[r][kq + 0] = f2tf(pa.x); As[r][kq + 1] = f2tf(pa.y);
            As[r][kq + 2] = f2tf(pa.z); As[r][kq + 3] = f2tf(pa.w);
        }
        #pragma unroll
        for (int j = 0; j < 2; j++) {
            int f = tid + 256 * j;
            int r = f >> 2, kq = (f & 3) << 2;
            Bs[r][kq + 0] = f2tf(pb[j].x); Bs[r][kq + 1] = f2tf(pb[j].y);
            Bs[r][kq + 2] = f2tf(pb[j].z); Bs[r][kq + 3] = f2tf(pb[j].w);
        }
        __syncthreads();

        if (k0 + 16 < K) {
            pa = *(const float4*)(Ab + (long)(tid >> 2) * lda + k0 + 16 + ((tid & 3) << 2));
            #pragma unroll
            for (int j = 0; j < 2; j++) {
                int f = tid + 256 * j;
                pb[j] = *(const float4*)(Bb + (long)(f >> 2) * ldb + k0 + 16 + ((f & 3) << 2));
            }
        }

        #pragma unroll
        for (int ks = 0; ks < 2; ks++) {
            const int c0 = ks * 8;
            uint32_t af[2][4], bf[4][2];
            #pragma unroll
            for (int mt = 0; mt < 2; mt++) {
                int r0 = wm * 32 + mt * 16 + g;
                af[mt][0] = __float_as_uint(As[r0][c0 + tig]);
                af[mt][1] = __float_as_uint(As[r0 + 8][c0 + tig]);
                af[mt][2] = __float_as_uint(As[r0][c0 + tig + 4]);
                af[mt][3] = __float_as_uint(As[r0 + 8][c0 + tig + 4]);
            }
            #pragma unroll
            for (int nt = 0; nt < 4; nt++) {
                int n = wn * 32 + nt * 8 + g;
                bf[nt][0] = __float_as_uint(Bs[n][c0 + tig]);
                bf[nt][1] = __float_as_uint(Bs[n][c0 + tig + 4]);
            }
            #pragma unroll
            for (int mt = 0; mt < 2; mt++)
                #pragma unroll
                for (int nt = 0; nt < 4; nt++)
                    mma8(acc[mt][nt], af[mt], bf[nt]);
        }
        __syncthreads();
    }

    const long cbase = (long)blockIdx.y * 64 * ldc + (long)blockIdx.x * 128;
    #pragma unroll
    for (int mt = 0; mt < 2; mt++)
        #pragma unroll
        for (int nt = 0; nt < 4; nt++) {
            long r0  = wm * 32 + mt * 16 + g;
            int  col = wn * 32 + nt * 8 + 2 * tig;
            if (HOUT) {
                __half* Cb = Ch + cbase;
                *(__half2*)&Cb[r0 * ldc + col] =
                    __floats2half2_rn(acc[mt][nt][0], acc[mt][nt][1]);
                *(__half2*)&Cb[(r0 + 8) * ldc + col] =
                    __floats2half2_rn(acc[mt][nt][2], acc[mt][nt][3]);
            } else {
                float* Cb = C + cbase;
                *(float2*)&Cb[r0 * ldc + col] =
                    make_float2(acc[mt][nt][0], acc[mt][nt][1]);
                *(float2*)&Cb[(r0 + 8) * ldc + col] =
                    make_float2(acc[mt][nt][2], acc[mt][nt][3]);
            }
        }
}

// ---------------------------------------------------------------------------
// L2 normalize each 64-float segment and emit fp16 (one warp per segment).
// ---------------------------------------------------------------------------
__global__ __launch_bounds__(256) void l2norm_h_kernel(const float* __restrict__ X,
                                                       __half* __restrict__ Y, float coef)
{
    const int seg  = blockIdx.x * 8 + (threadIdx.x >> 5);
    const int lane = threadIdx.x & 31;
    float2 u = *((const float2*)(X + (long)seg * 64) + lane);
    float ss = u.x * u.x + u.y * u.y;
    #pragma unroll
    for (int o = 16; o; o >>= 1) ss += __shfl_xor_sync(0xffffffffu, ss, o);
    const float s = coef / fmaxf(sqrtf(ss), 1e-12f);
    *((__half2*)(Y + (long)seg * 64) + lane) = __floats2half2_rn(u.x * s, u.y * s);
}

// ---------------------------------------------------------------------------
// Fused flash attention (no-max softmax; scores bounded by 1/8):
// per (b,h,128-q tile): loop 64-k tiles: S=Q.K^T (fp16 MMA), E=exp(S) ->
// gmem (for avg) + register repack -> O += E.V (fp16 MMA), Z += rowsum(E).
// Epilogue: out = O/Z, invZ stored for the avg pass.
// 256 threads = 8 warps, each warp owns 16 q rows.  grid (CL/128, BHn).
// ---------------------------------------------------------------------------
__global__ __launch_bounds__(256) void flash_kernel(
    const __half* __restrict__ Qh, const __half* __restrict__ Kh,
    const __half* __restrict__ Vh, __half* __restrict__ E,
    float* __restrict__ invZ, float* __restrict__ out)
{
    __shared__ __half Qs[128][72];
    __shared__ __half Ks[64][72];
    __shared__ __half Vs[64][72];

    const int z = blockIdx.y, b = z >> 4, h = z & 15;
    const int qbase = blockIdx.x * 128;
    const int tid = threadIdx.x, w = tid >> 5, lane = tid & 31;
    const int g = lane >> 2, tig = lane & 3;

    // stage Q tile, pull per-warp A fragments (held for the whole kernel)
    const __half* Qg = Qh + ((long)b * CL + qbase) * CD + h * 64;
    #pragma unroll
    for (int j = 0; j < 4; j++) {
        int f = tid + 256 * j;
        int r = f >> 3, c = (f & 7) * 8;
        *(uint4*)&Qs[r][c] = *(const uint4*)(Qg + (long)r * CD + c);
    }
    __syncthreads();
    uint32_t aq[4][4];
    #pragma unroll
    for (int kc = 0; kc < 4; kc++)
        ldm4(aq[kc], sptr(&Qs[w * 16 + (lane & 15)][kc * 16 + (lane >> 4) * 8]));

    const __half* Kg = Kh + (long)b * CL * CD + h * 64;
    const __half* Vg = Vh + (long)b * CL * CD + h * 64;

    float acc_o[8][4];
    #pragma unroll
    for (int i = 0; i < 8; i++)
        #pragma unroll
        for (int r = 0; r < 4; r++) acc_o[i][r] = 0.f;
    float zr0 = 0.f, zr1 = 0.f;

    uint4 pk[2], pv[2];
    #pragma unroll
    for (int j = 0; j < 2; j++) {
        int f = tid + 256 * j;
        int r = f >> 3, c = (f & 7) * 8;
        pk[j] = *(const uint4*)(Kg + (long)r * CD + c);
        pv[j] = *(const uint4*)(Vg + (long)r * CD + c);
    }

    __half* Eb = E + (long)z * CL * CL + (long)(qbase + w * 16 + g) * CL;

    for (int kt = 0; kt < CL / 64; kt++) {
        #pragma unroll
        for (int j = 0; j < 2; j++) {
            int f = tid + 256 * j;
            int r = f >> 3, c = (f & 7) * 8;
            *(uint4*)&Ks[r][c] = pk[j];
            *(uint4*)&Vs[r][c] = pv[j];
        }
        __syncthreads();

        if (kt + 1 < CL / 64) {
            #pragma unroll
            for (int j = 0; j < 2; j++) {
                int f = tid + 256 * j;
                int r = f >> 3, c = (f & 7) * 8;
                long row = (long)((kt + 1) * 64 + r);
                pk[j] = *(const uint4*)(Kg + row * CD + c);
                pv[j] = *(const uint4*)(Vg + row * CD + c);
            }
        }

        // scores: S[16q x 64k] per warp
        float s[8][4];
        #pragma unroll
        for (int i = 0; i < 8; i++)
            #pragma unroll
            for (int r = 0; r < 4; r++) s[i][r] = 0.f;

        #pragma unroll
        for (int kc = 0; kc < 4; kc++) {
            #pragma unroll
            for (int p = 0; p < 4; p++) {
                uint32_t r4[4];
                ldm4(r4, sptr(&Ks[p * 16 + (lane & 15)][kc * 16 + (lane >> 4) * 8]));
                uint32_t b0[2] = {r4[0], r4[2]}, b1[2] = {r4[1], r4[3]};
                mma16h(s[2 * p],     aq[kc], b0);
                mma16h(s[2 * p + 1], aq[kc], b1);
            }
        }

        // exp + pack to fp16 A-fragments + write E + row-sum accumulation
        uint32_t ehlo[8], ehhi[8];
        #pragma unroll
        for (int nt = 0; nt < 8; nt++) {
            float e0 = __expf(s[nt][0]);
            float e1 = __expf(s[nt][1]);
            float e2 = __expf(s[nt][2]);
            float e3 = __expf(s[nt][3]);
            __half2 lo = __floats2half2_rn(e0, e1);
            __half2 hi = __floats2half2_rn(e2, e3);
            ehlo[nt] = *(uint32_t*)&lo;
            ehhi[nt] = *(uint32_t*)&hi;
            zr0 += e0 + e1;
            zr1 += e2 + e3;
            __half* p0 = Eb + kt * 64 + nt * 8 + 2 * tig;
            *(uint32_t*)p0            = ehlo[nt];
            *(uint32_t*)(p0 + 8 * CL) = ehhi[nt];
        }

        // PV: O += E . V  (B via ldmatrix.trans on V[k][n])
        #pragma unroll
        for (int kc = 0; kc < 4; kc++) {
            uint32_t a[4] = {ehlo[2 * kc], ehhi[2 * kc], ehlo[2 * kc + 1], ehhi[2 * kc + 1]};
            #pragma unroll
            for (int p = 0; p < 4; p++) {
                uint32_t r4[4];
                ldm4t(r4, sptr(&Vs[kc * 16 + (lane & 15)][p * 16 + (lane >> 4) * 8]));
                uint32_t b0[2] = {r4[0], r4[1]}, b1[2] = {r4[2], r4[3]};
                mma16h(acc_o[2 * p],     a, b0);
                mma16h(acc_o[2 * p + 1], a, b1);
            }
        }
        __syncthreads();
    }

    // row sums across the 4 tig lanes (fixed order), then normalize + write
    zr0 += __shfl_xor_sync(0xffffffffu, zr0, 1);
    zr0 += __shfl_xor_sync(0xffffffffu, zr0, 2);
    zr1 += __shfl_xor_sync(0xffffffffu, zr1, 1);
    zr1 += __shfl_xor_sync(0xffffffffu, zr1, 2);
    const float iz0 = 1.0f / zr0;
    const float iz1 = 1.0f / zr1;
    if (tig == 0) {
        invZ[(long)z * CL + qbase + w * 16 + g]     = iz0;
        invZ[(long)z * CL + qbase + w * 16 + g + 8] = iz1;
    }
    float* Ob = out + (long)z * CL * CDK + (long)(qbase + w * 16) * CDK;
    #pragma unroll
    for (int nt = 0; nt < 8; nt++) {
        int col = nt * 8 + 2 * tig;
        *(float2*)&Ob[(long)g * CDK + col] =
            make_float2(acc_o[nt][0] * iz0, acc_o[nt][1] * iz0);
        *(float2*)&Ob[(long)(g + 8) * CDK + col] =
            make_float2(acc_o[nt][2] * iz1, acc_o[nt][3] * iz1);
    }
}

// ---------------------------------------------------------------------------
// avg[b,q,k] = (1/16) * sum_h E[b,h,q,k] * invZ[b,h,q].  Block per (b,q),
// thread t covers cols t*8..t*8+7 (uint4 loads).
// ---------------------------------------------------------------------------
__global__ __launch_bounds__(256) void avg_kernel(const __half* __restrict__ E,
                                                  const float* __restrict__ invZ,
                                                  float* __restrict__ avg)
{
    const int b = blockIdx.x >> 11, q = blockIdx.x & 2047;
    const int t = threadIdx.x;
    __shared__ float wz[16];
    if (t < 16)
        wz[t] = invZ[(long)(b * 16 + t) * CL + q] * (1.0f / 16.0f);
    __syncthreads();

    float a[8];
    #pragma unroll
    for (int i = 0; i < 8; i++) a[i] = 0.f;

    #pragma unroll
    for (int h = 0; h < 16; h++) {
        const __half2* row =
            (const __half2*)(E + ((long)(b * 16 + h) * CL + q) * CL + t * 8);
        const float wh = wz[h];
        uint4 u = *(const uint4*)row;
        const __half2* hp = (const __half2*)&u;
        #pragma unroll
        for (int i = 0; i < 4; i++) {
            float2 f = __half22float2(hp[i]);
            a[2 * i]     += wh * f.x;
            a[2 * i + 1] += wh * f.y;
        }
    }
    float* arow = avg + ((long)b * CL + q) * CL + t * 8;
    *(float4*)arow       = make_float4(a[0], a[1], a[2], a[3]);
    *(float4*)(arow + 4) = make_float4(a[4], a[5], a[6], a[7]);
}

// ---------------------------------------------------------------------------
extern "C" void kernel_launch(void* const* d_in, const int* in_sizes, int n_in,
                              void* d_out, int out_size)
{
    const float* q  = (const float*)d_in[0];
    const float* k  = (const float*)d_in[1];
    const float* v  = (const float*)d_in[2];
    const float* wq = (const float*)d_in[3];
    const float* wk = (const float*)d_in[4];
    const float* wv = (const float*)d_in[5];

    float* out = (float*)d_out;                        // [B,H,L,64]
    float* avg = out + (long)CB * CH * CL * CDK;       // [B,L,L]

    float *Qp, *Kp, *iZ;
    __half *Qh, *Kh, *Vh, *Ep;
    cudaGetSymbolAddress((void**)&Qp, g_Q);
    cudaGetSymbolAddress((void**)&Kp, g_K);
    cudaGetSymbolAddress((void**)&Qh, g_Qh);
    cudaGetSymbolAddress((void**)&Kh, g_Kh);
    cudaGetSymbolAddress((void**)&Vh, g_Vh);
    cudaGetSymbolAddress((void**)&Ep, g_E);
    cudaGetSymbolAddress((void**)&iZ, g_invZ);

    // 1) Projections (tf32 MMA); V writes fp16 directly
    dim3 pg(CD / 128, (CB * CL) / 64, 1);
    mma_gemm_nt<false><<<pg, 256>>>(q, wq, Qp, nullptr, CD, CD, CD, CD);
    mma_gemm_nt<false><<<pg, 256>>>(k, wk, Kp, nullptr, CD, CD, CD, CD);
    mma_gemm_nt<true ><<<pg, 256>>>(v, wv, nullptr, Vh, CD, CD, CD, CD);

    // 2) L2 normalize -> fp16 (fold 1/sqrt(64)=0.125 into Q)
    l2norm_h_kernel<<<(CB * CL * CH) / 8, 256>>>(Qp, Qh, 0.125f);
    l2norm_h_kernel<<<(CB * CL * CH) / 8, 256>>>(Kp, Kh, 1.0f);

    // 3) Fused attention: E (fp16) + invZ + out
    dim3 fg(CL / 128, BHn);
    flash_kernel<<<fg, 256>>>(Qh, Kh, Vh, Ep, iZ, out);

    // 4) attn_avg from E and invZ
    avg_kernel<<<CB * CL, 256>>>(Ep, iZ, avg);
}

// round 8
// speedup vs baseline: 4.7036x; 1.5285x over previous
#include <cuda_runtime.h>
#include <cuda_fp16.h>
#include <stdint.h>

// Problem constants
#define CB 2
#define CL 2048
#define CD 1024
#define CH 16
#define CDK 64

constexpr int  BHn        = CB * CH;               // 32
constexpr long PROJ_ELEMS = (long)CB * CL * CD;    // 4,194,304
constexpr long S_ELEMS    = (long)BHn * CL * CL;   // 134,217,728
constexpr long ZN         = (long)BHn * CL;        // 65,536

// Scratch (static device globals -- no runtime allocation)
__device__ __half g_Qh[PROJ_ELEMS];                // Q proj -> normalized, fp16
__device__ __half g_Kh[PROJ_ELEMS];                // K proj -> normalized, fp16
__device__ __half g_Vh[PROJ_ELEMS];                // V projection, fp16
__device__ __half g_E[S_ELEMS];                    // exp(scores), fp16
__device__ float  g_invZ[ZN];

// ---------------------------------------------------------------------------
// helpers
// ---------------------------------------------------------------------------
__device__ __forceinline__ void mma16h(float* d, const uint32_t* a, const uint32_t* b) {
    asm volatile(
        "mma.sync.aligned.m16n8k16.row.col.f32.f16.f16.f32 "
        "{%0,%1,%2,%3}, {%4,%5,%6,%7}, {%8,%9}, {%0,%1,%2,%3};"
        : "+f"(d[0]), "+f"(d[1]), "+f"(d[2]), "+f"(d[3])
        : "r"(a[0]), "r"(a[1]), "r"(a[2]), "r"(a[3]), "r"(b[0]), "r"(b[1]));
}

__device__ __forceinline__ uint32_t sptr(const void* p) {
    return (uint32_t)__cvta_generic_to_shared(p);
}

__device__ __forceinline__ void ldm4(uint32_t* a, uint32_t addr) {
    asm volatile("ldmatrix.sync.aligned.m8n8.x4.shared.b16 {%0,%1,%2,%3}, [%4];"
                 : "=r"(a[0]), "=r"(a[1]), "=r"(a[2]), "=r"(a[3]) : "r"(addr));
}

__device__ __forceinline__ void ldm4t(uint32_t* a, uint32_t addr) {
    asm volatile("ldmatrix.sync.aligned.m8n8.x4.trans.shared.b16 {%0,%1,%2,%3}, [%4];"
                 : "=r"(a[0]), "=r"(a[1]), "=r"(a[2]), "=r"(a[3]) : "r"(addr));
}

// ---------------------------------------------------------------------------
// fp16-MMA NT projection GEMM: C[m,n] = half( sum_k A[m,k]*B[n,k] )
// A,B fp32 in gmem (converted to fp16 during smem staging; fp16 mantissa ==
// tf32 mantissa, so no extra error vs tf32). BM=64, BN=128, BK=32,
// 256 threads (2x4 warps), ldmatrix fragments, fp32 accum, fp16 out.
// ---------------------------------------------------------------------------
__global__ __launch_bounds__(256) void proj_h_kernel(
    const float* __restrict__ A, const float* __restrict__ B,
    __half* __restrict__ C)
{
    __shared__ __half As[64][40];
    __shared__ __half Bs[128][40];

    const float* Ab = A + (long)blockIdx.y * 64 * CD;
    const float* Bb = B + (long)blockIdx.x * 128 * CD;

    const int tid  = threadIdx.x;
    const int w    = tid >> 5, lane = tid & 31;
    const int wm   = w >> 2, wn = w & 3;
    const int g    = lane >> 2, tig = lane & 3;

    float acc[2][4][4];
    #pragma unroll
    for (int i = 0; i < 2; i++)
        #pragma unroll
        for (int j = 0; j < 4; j++)
            #pragma unroll
            for (int r = 0; r < 4; r++) acc[i][j][r] = 0.f;

    float4 pa[2], pb[4];
    #pragma unroll
    for (int j = 0; j < 2; j++) {
        int s = tid + 256 * j;                       // A float4 slot: 512 total
        pa[j] = *(const float4*)(Ab + (long)(s >> 3) * CD + (s & 7) * 4);
    }
    #pragma unroll
    for (int j = 0; j < 4; j++) {
        int s = tid + 256 * j;                       // B float4 slot: 1024 total
        pb[j] = *(const float4*)(Bb + (long)(s >> 3) * CD + (s & 7) * 4);
    }

    for (int k0 = 0; k0 < CD; k0 += 32) {
        #pragma unroll
        for (int j = 0; j < 2; j++) {
            int s = tid + 256 * j;
            int r = s >> 3, c = (s & 7) * 4;
            As[r][c + 0] = __float2half(pa[j].x);
            As[r][c + 1] = __float2half(pa[j].y);
            As[r][c + 2] = __float2half(pa[j].z);
            As[r][c + 3] = __float2half(pa[j].w);
        }
        #pragma unroll
        for (int j = 0; j < 4; j++) {
            int s = tid + 256 * j;
            int r = s >> 3, c = (s & 7) * 4;
            Bs[r][c + 0] = __float2half(pb[j].x);
            Bs[r][c + 1] = __float2half(pb[j].y);
            Bs[r][c + 2] = __float2half(pb[j].z);
            Bs[r][c + 3] = __float2half(pb[j].w);
        }
        __syncthreads();

        if (k0 + 32 < CD) {
            #pragma unroll
            for (int j = 0; j < 2; j++) {
                int s = tid + 256 * j;
                pa[j] = *(const float4*)(Ab + (long)(s >> 3) * CD + k0 + 32 + (s & 7) * 4);
            }
            #pragma unroll
            for (int j = 0; j < 4; j++) {
                int s = tid + 256 * j;
                pb[j] = *(const float4*)(Bb + (long)(s >> 3) * CD + k0 + 32 + (s & 7) * 4);
            }
        }

        #pragma unroll
        for (int ks = 0; ks < 2; ks++) {
            const int c0 = ks * 16;
            uint32_t af[2][4], bf[4][2];
            #pragma unroll
            for (int mt = 0; mt < 2; mt++)
                ldm4(af[mt], sptr(&As[wm * 32 + mt * 16 + (lane & 15)][c0 + (lane >> 4) * 8]));
            #pragma unroll
            for (int nh = 0; nh < 2; nh++) {
                uint32_t r4[4];
                ldm4(r4, sptr(&Bs[wn * 32 + nh * 16 + (lane & 15)][c0 + (lane >> 4) * 8]));
                bf[2 * nh][0]     = r4[0]; bf[2 * nh][1]     = r4[2];
                bf[2 * nh + 1][0] = r4[1]; bf[2 * nh + 1][1] = r4[3];
            }
            #pragma unroll
            for (int mt = 0; mt < 2; mt++)
                #pragma unroll
                for (int nt = 0; nt < 4; nt++)
                    mma16h(acc[mt][nt], af[mt], bf[nt]);
        }
        __syncthreads();
    }

    __half* Cb = C + (long)blockIdx.y * 64 * CD + (long)blockIdx.x * 128;
    #pragma unroll
    for (int mt = 0; mt < 2; mt++)
        #pragma unroll
        for (int nt = 0; nt < 4; nt++) {
            long r0  = wm * 32 + mt * 16 + g;
            int  col = wn * 32 + nt * 8 + 2 * tig;
            *(__half2*)&Cb[r0 * CD + col] =
                __floats2half2_rn(acc[mt][nt][0], acc[mt][nt][1]);
            *(__half2*)&Cb[(r0 + 8) * CD + col] =
                __floats2half2_rn(acc[mt][nt][2], acc[mt][nt][3]);
        }
}

// ---------------------------------------------------------------------------
// In-place L2 normalize of each 64-half segment (one warp per segment).
// ---------------------------------------------------------------------------
__global__ __launch_bounds__(256) void l2norm_h_kernel(__half* __restrict__ X, float coef)
{
    const int seg  = blockIdx.x * 8 + (threadIdx.x >> 5);
    const int lane = threadIdx.x & 31;
    __half2* p = (__half2*)(X + (long)seg * 64) + lane;
    float2 u = __half22float2(*p);
    float ss = u.x * u.x + u.y * u.y;
    #pragma unroll
    for (int o = 16; o; o >>= 1) ss += __shfl_xor_sync(0xffffffffu, ss, o);
    const float s = coef / fmaxf(sqrtf(ss), 1e-12f);
    *p = __floats2half2_rn(u.x * s, u.y * s);
}

// ---------------------------------------------------------------------------
// Fused flash attention (no-max softmax; scores bounded by 1/8):
// per (b,h,128-q tile): loop 64-k tiles: S=Q.K^T (fp16 MMA), E=exp(S) ->
// gmem (for avg) + register repack -> O += E.V (fp16 MMA), Z += rowsum(E).
// Epilogue: out = O/Z, invZ stored for the avg pass.
// 256 threads = 8 warps, each warp owns 16 q rows.  grid (CL/128, BHn).
// ---------------------------------------------------------------------------
__global__ __launch_bounds__(256) void flash_kernel(
    const __half* __restrict__ Qh, const __half* __restrict__ Kh,
    const __half* __restrict__ Vh, __half* __restrict__ E,
    float* __restrict__ invZ, float* __restrict__ out)
{
    __shared__ __half Qs[128][72];
    __shared__ __half Ks[64][72];
    __shared__ __half Vs[64][72];

    const int z = blockIdx.y, b = z >> 4, h = z & 15;
    const int qbase = blockIdx.x * 128;
    const int tid = threadIdx.x, w = tid >> 5, lane = tid & 31;
    const int g = lane >> 2, tig = lane & 3;

    // stage Q tile, pull per-warp A fragments (held for the whole kernel)
    const __half* Qg = Qh + ((long)b * CL + qbase) * CD + h * 64;
    #pragma unroll
    for (int j = 0; j < 4; j++) {
        int f = tid + 256 * j;
        int r = f >> 3, c = (f & 7) * 8;
        *(uint4*)&Qs[r][c] = *(const uint4*)(Qg + (long)r * CD + c);
    }
    __syncthreads();
    uint32_t aq[4][4];
    #pragma unroll
    for (int kc = 0; kc < 4; kc++)
        ldm4(aq[kc], sptr(&Qs[w * 16 + (lane & 15)][kc * 16 + (lane >> 4) * 8]));

    const __half* Kg = Kh + (long)b * CL * CD + h * 64;
    const __half* Vg = Vh + (long)b * CL * CD + h * 64;

    float acc_o[8][4];
    #pragma unroll
    for (int i = 0; i < 8; i++)
        #pragma unroll
        for (int r = 0; r < 4; r++) acc_o[i][r] = 0.f;
    float zr0 = 0.f, zr1 = 0.f;

    uint4 pk[2], pv[2];
    #pragma unroll
    for (int j = 0; j < 2; j++) {
        int f = tid + 256 * j;
        int r = f >> 3, c = (f & 7) * 8;
        pk[j] = *(const uint4*)(Kg + (long)r * CD + c);
        pv[j] = *(const uint4*)(Vg + (long)r * CD + c);
    }

    __half* Eb = E + (long)z * CL * CL + (long)(qbase + w * 16 + g) * CL;

    for (int kt = 0; kt < CL / 64; kt++) {
        #pragma unroll
        for (int j = 0; j < 2; j++) {
            int f = tid + 256 * j;
            int r = f >> 3, c = (f & 7) * 8;
            *(uint4*)&Ks[r][c] = pk[j];
            *(uint4*)&Vs[r][c] = pv[j];
        }
        __syncthreads();

        if (kt + 1 < CL / 64) {
            #pragma unroll
            for (int j = 0; j < 2; j++) {
                int f = tid + 256 * j;
                int r = f >> 3, c = (f & 7) * 8;
                long row = (long)((kt + 1) * 64 + r);
                pk[j] = *(const uint4*)(Kg + row * CD + c);
                pv[j] = *(const uint4*)(Vg + row * CD + c);
            }
        }

        // scores: S[16q x 64k] per warp
        float s[8][4];
        #pragma unroll
        for (int i = 0; i < 8; i++)
            #pragma unroll
            for (int r = 0; r < 4; r++) s[i][r] = 0.f;

        #pragma unroll
        for (int kc = 0; kc < 4; kc++) {
            #pragma unroll
            for (int p = 0; p < 4; p++) {
                uint32_t r4[4];
                ldm4(r4, sptr(&Ks[p * 16 + (lane & 15)][kc * 16 + (lane >> 4) * 8]));
                uint32_t b0[2] = {r4[0], r4[2]}, b1[2] = {r4[1], r4[3]};
                mma16h(s[2 * p],     aq[kc], b0);
                mma16h(s[2 * p + 1], aq[kc], b1);
            }
        }

        // exp + pack to fp16 A-fragments + write E + row-sum accumulation
        uint32_t ehlo[8], ehhi[8];
        #pragma unroll
        for (int nt = 0; nt < 8; nt++) {
            float e0 = __expf(s[nt][0]);
            float e1 = __expf(s[nt][1]);
            float e2 = __expf(s[nt][2]);
            float e3 = __expf(s[nt][3]);
            __half2 lo = __floats2half2_rn(e0, e1);
            __half2 hi = __floats2half2_rn(e2, e3);
            ehlo[nt] = *(uint32_t*)&lo;
            ehhi[nt] = *(uint32_t*)&hi;
            zr0 += e0 + e1;
            zr1 += e2 + e3;
            __half* p0 = Eb + kt * 64 + nt * 8 + 2 * tig;
            *(uint32_t*)p0            = ehlo[nt];
            *(uint32_t*)(p0 + 8 * CL) = ehhi[nt];
        }

        // PV: O += E . V  (B via ldmatrix.trans on V[k][n])
        #pragma unroll
        for (int kc = 0; kc < 4; kc++) {
            uint32_t a[4] = {ehlo[2 * kc], ehhi[2 * kc], ehlo[2 * kc + 1], ehhi[2 * kc + 1]};
            #pragma unroll
            for (int p = 0; p < 4; p++) {
                uint32_t r4[4];
                ldm4t(r4, sptr(&Vs[kc * 16 + (lane & 15)][p * 16 + (lane >> 4) * 8]));
                uint32_t b0[2] = {r4[0], r4[1]}, b1[2] = {r4[2], r4[3]};
                mma16h(acc_o[2 * p],     a, b0);
                mma16h(acc_o[2 * p + 1], a, b1);
            }
        }
        __syncthreads();
    }

    // row sums across the 4 tig lanes (fixed order), then normalize + write
    zr0 += __shfl_xor_sync(0xffffffffu, zr0, 1);
    zr0 += __shfl_xor_sync(0xffffffffu, zr0, 2);
    zr1 += __shfl_xor_sync(0xffffffffu, zr1, 1);
    zr1 += __shfl_xor_sync(0xffffffffu, zr1, 2);
    const float iz0 = 1.0f / zr0;
    const float iz1 = 1.0f / zr1;
    if (tig == 0) {
        invZ[(long)z * CL + qbase + w * 16 + g]     = iz0;
        invZ[(long)z * CL + qbase + w * 16 + g + 8] = iz1;
    }
    float* Ob = out + (long)z * CL * CDK + (long)(qbase + w * 16) * CDK;
    #pragma unroll
    for (int nt = 0; nt < 8; nt++) {
        int col = nt * 8 + 2 * tig;
        *(float2*)&Ob[(long)g * CDK + col] =
            make_float2(acc_o[nt][0] * iz0, acc_o[nt][1] * iz0);
        *(float2*)&Ob[(long)(g + 8) * CDK + col] =
            make_float2(acc_o[nt][2] * iz1, acc_o[nt][3] * iz1);
    }
}

// ---------------------------------------------------------------------------
// avg[b,q,k] = (1/16) * sum_h E[b,h,q,k] * invZ[b,h,q].  Block per (b,q),
// thread t covers cols t*8..t*8+7 (uint4 loads).
// ---------------------------------------------------------------------------
__global__ __launch_bounds__(256) void avg_kernel(const __half* __restrict__ E,
                                                  const float* __restrict__ invZ,
                                                  float* __restrict__ avg)
{
    const int b = blockIdx.x >> 11, q = blockIdx.x & 2047;
    const int t = threadIdx.x;
    __shared__ float wz[16];
    if (t < 16)
        wz[t] = invZ[(long)(b * 16 + t) * CL + q] * (1.0f / 16.0f);
    __syncthreads();

    float a[8];
    #pragma unroll
    for (int i = 0; i < 8; i++) a[i] = 0.f;

    #pragma unroll
    for (int h = 0; h < 16; h++) {
        const __half2* row =
            (const __half2*)(E + ((long)(b * 16 + h) * CL + q) * CL + t * 8);
        const float wh = wz[h];
        uint4 u = *(const uint4*)row;
        const __half2* hp = (const __half2*)&u;
        #pragma unroll
        for (int i = 0; i < 4; i++) {
            float2 f = __half22float2(hp[i]);
            a[2 * i]     += wh * f.x;
            a[2 * i + 1] += wh * f.y;
        }
    }
    float* arow = avg + ((long)b * CL + q) * CL + t * 8;
    *(float4*)arow       = make_float4(a[0], a[1], a[2], a[3]);
    *(float4*)(arow + 4) = make_float4(a[4], a[5], a[6], a[7]);
}

// ---------------------------------------------------------------------------
extern "C" void kernel_launch(void* const* d_in, const int* in_sizes, int n_in,
                              void* d_out, int out_size)
{
    const float* q  = (const float*)d_in[0];
    const float* k  = (const float*)d_in[1];
    const float* v  = (const float*)d_in[2];
    const float* wq = (const float*)d_in[3];
    const float* wk = (const float*)d_in[4];
    const float* wv = (const float*)d_in[5];

    float* out = (float*)d_out;                        // [B,H,L,64]
    float* avg = out + (long)CB * CH * CL * CDK;       // [B,L,L]

    float  *iZ;
    __half *Qh, *Kh, *Vh, *Ep;
    cudaGetSymbolAddress((void**)&Qh, g_Qh);
    cudaGetSymbolAddress((void**)&Kh, g_Kh);
    cudaGetSymbolAddress((void**)&Vh, g_Vh);
    cudaGetSymbolAddress((void**)&Ep, g_E);
    cudaGetSymbolAddress((void**)&iZ, g_invZ);

    // 1) Projections (fp16 MMA, fp32 accumulate, fp16 out)
    dim3 pg(CD / 128, (CB * CL) / 64, 1);
    proj_h_kernel<<<pg, 256>>>(q, wq, Qh);
    proj_h_kernel<<<pg, 256>>>(k, wk, Kh);
    proj_h_kernel<<<pg, 256>>>(v, wv, Vh);

    // 2) In-place L2 normalize (fold 1/sqrt(64)=0.125 into Q)
    l2norm_h_kernel<<<(CB * CL * CH) / 8, 256>>>(Qh, 0.125f);
    l2norm_h_kernel<<<(CB * CL * CH) / 8, 256>>>(Kh, 1.0f);

    // 3) Fused attention: E (fp16) + invZ + out
    dim3 fg(CL / 128, BHn);
    flash_kernel<<<fg, 256>>>(Qh, Kh, Vh, Ep, iZ, out);

    // 4) attn_avg from E and invZ
    avg_kernel<<<CB * CL, 256>>>(Ep, iZ, avg);
}